// round 8
// baseline (speedup 1.0000x reference)
#include <cuda_runtime.h>
#include <cuda_bf16.h>
#include <cstdint>
#include <cstddef>

// Problem constants
#define Bb   2
#define Ss   2048
#define Hh   2048
#define NHh  16
#define HDd  128
#define Pp   2048
#define Mm   (Bb * Ss)          // 4096 rows
#define H2   (Hh / 2)           // 1024
#define QKW  (2 * Pp)           // 4096 (qk row width)
#define EPSc 1e-6f

// ---------------- scratch (static device globals; no allocation) ----------------
__device__ float g_v[(size_t)Mm * Pp];
__device__ float g_xprev[(size_t)Mm * Hh];
__device__ float g_y1[(size_t)Mm * H2];
__device__ float g_y1prev[(size_t)Mm * H2];
__device__ float g_lfout[(size_t)Mm * Hh];
__device__ float g_qk[(size_t)Mm * QKW];
__device__ float g_attn[(size_t)Mm * Pp];
__device__ float g_w1a[(size_t)H2 * Hh];
__device__ float g_w1b[(size_t)H2 * Hh];
__device__ float g_w2a[(size_t)Hh * H2];
__device__ float g_w2b[(size_t)Hh * H2];

// ---------------- helpers ----------------
__device__ __forceinline__ uint32_t f2tf(float x) {
    uint32_t r;
    asm("cvt.rna.tf32.f32 %0, %1;" : "=r"(r) : "f"(x));
    return r;
}

__device__ __forceinline__ void mma_tf32(float* d, const uint32_t* a, const uint32_t* b) {
    asm volatile(
        "mma.sync.aligned.m16n8k8.row.col.f32.tf32.tf32.f32 "
        "{%0,%1,%2,%3},{%4,%5,%6,%7},{%8,%9},{%0,%1,%2,%3};"
        : "+f"(d[0]), "+f"(d[1]), "+f"(d[2]), "+f"(d[3])
        : "r"(a[0]), "r"(a[1]), "r"(a[2]), "r"(a[3]), "r"(b[0]), "r"(b[1]));
}

__device__ __forceinline__ void sts_cvt(uint32_t* p, float4 v) {
    uint4 u;
    u.x = f2tf(v.x); u.y = f2tf(v.y); u.z = f2tf(v.z); u.w = f2tf(v.w);
    *(uint4*)p = u;
}

// ---------------- deinterleave conv weights ----------------
__global__ void deint_kernel(const float* __restrict__ in, float* __restrict__ a,
                             float* __restrict__ b, int n)
{
    int i = blockIdx.x * 256 + threadIdx.x;
    if (i < n) {
        a[i] = in[2 * i];
        b[i] = in[2 * i + 1];
    }
}

// ---------------- shift rows by one seq step ----------------
__global__ void shift_kernel(const float* __restrict__ x, const float* __restrict__ cache,
                             float* __restrict__ out, int width)
{
    int m = blockIdx.x;
    int s = m % Ss;
    int b = m / Ss;
    const float* src = (s == 0) ? (cache + (size_t)b * width)
                                : (x + (size_t)(m - 1) * width);
    float* dst = out + (size_t)m * width;
    for (int i = threadIdx.x; i < width; i += 256) dst[i] = src[i];
}

// ========== TF32 tensor-core GEMM v2 (NT), 256x128 block, warp tile 64x64 ==========
// C[M,N] = A[M,K] * W[N,K]^T (+ A2[M,K] * W2[N,K]^T) (+bias)
// 8 warps (4x2), BK=16, double-buffered smem, LDG register prefetch.
// M%256==0, N%128==0, K%16==0.
#define BM2 256
#define BN2 128
#define BK2 16
#define PAD2 20
// dynamic smem (u32 words): A0 | A1 | B0 | B1
#define A2_W (BM2 * PAD2)            // 5120
#define B2_W (BN2 * PAD2)            // 2560
#define G2_SMEM ((2 * A2_W + 2 * B2_W) * 4)   // 61440 bytes

__global__ __launch_bounds__(256, 1) void gemm_v2_kernel(
    const float* __restrict__ A, const float* __restrict__ W,
    const float* __restrict__ A2, const float* __restrict__ W2,
    float* __restrict__ C, int N, int K, const float* __restrict__ bias)
{
    extern __shared__ uint32_t sm2[];
    uint32_t* Asm[2] = {sm2, sm2 + A2_W};
    uint32_t* Bsm[2] = {sm2 + 2 * A2_W, sm2 + 2 * A2_W + B2_W};

    const int tid = threadIdx.x;
    const int lane = tid & 31;
    const int warp = tid >> 5;
    const int wm = warp >> 1;           // 0..3 (M direction, 64 rows each)
    const int wn = warp & 1;            // 0..1 (N direction, 64 cols each)
    const int bm = blockIdx.y * BM2;
    const int bn = blockIdx.x * BN2;
    const int mBase = wm * 64;
    const int nBase = wn * 64;

    // staging coords: A chunks idx = tid + i*256, i<4 ; B chunks i<2
    const int rs = tid >> 2;            // 0..63 base row
    const int cs = (tid & 3) << 2;      // 0,4,8,12

    float acc[4][8][4];
#pragma unroll
    for (int mi = 0; mi < 4; mi++)
#pragma unroll
        for (int ni = 0; ni < 8; ni++)
#pragma unroll
            for (int e = 0; e < 4; e++) acc[mi][ni][e] = 0.f;

    const int nk = K / BK2;
    const int nkt = A2 ? (2 * nk) : nk;

    // prefetch kt = 0
    float4 pa[4], pb[2];
#pragma unroll
    for (int i = 0; i < 4; i++)
        pa[i] = *(const float4*)(A + (size_t)(bm + rs + i * 64) * K + cs);
#pragma unroll
    for (int i = 0; i < 2; i++)
        pb[i] = *(const float4*)(W + (size_t)(bn + rs + i * 64) * K + cs);

    const int row4 = lane >> 2;
    const int col4 = lane & 3;

    for (int kt = 0; kt < nkt; kt++) {
        int buf = kt & 1;
        uint32_t* as = Asm[buf];
        uint32_t* bs = Bsm[buf];
#pragma unroll
        for (int i = 0; i < 4; i++)
            sts_cvt(&as[(rs + i * 64) * PAD2 + cs], pa[i]);
#pragma unroll
        for (int i = 0; i < 2; i++)
            sts_cvt(&bs[(rs + i * 64) * PAD2 + cs], pb[i]);
        __syncthreads();

        if (kt + 1 < nkt) {
            int k2 = kt + 1;
            const float* Ap; const float* Wp; int ko;
            if (k2 < nk) { Ap = A;  Wp = W;  ko = k2 * BK2; }
            else         { Ap = A2; Wp = W2; ko = (k2 - nk) * BK2; }
#pragma unroll
            for (int i = 0; i < 4; i++)
                pa[i] = *(const float4*)(Ap + (size_t)(bm + rs + i * 64) * K + ko + cs);
#pragma unroll
            for (int i = 0; i < 2; i++)
                pb[i] = *(const float4*)(Wp + (size_t)(bn + rs + i * 64) * K + ko + cs);
        }

#pragma unroll
        for (int kk = 0; kk < BK2; kk += 8) {
            uint32_t af[4][4], bf[8][2];
#pragma unroll
            for (int mi = 0; mi < 4; mi++) {
                int m0 = mBase + mi * 16;
                af[mi][0] = as[(m0 + row4) * PAD2 + kk + col4];
                af[mi][1] = as[(m0 + row4 + 8) * PAD2 + kk + col4];
                af[mi][2] = as[(m0 + row4) * PAD2 + kk + col4 + 4];
                af[mi][3] = as[(m0 + row4 + 8) * PAD2 + kk + col4 + 4];
            }
#pragma unroll
            for (int ni = 0; ni < 8; ni++) {
                int n0 = nBase + ni * 8;
                bf[ni][0] = bs[(n0 + row4) * PAD2 + kk + col4];
                bf[ni][1] = bs[(n0 + row4) * PAD2 + kk + col4 + 4];
            }
#pragma unroll
            for (int mi = 0; mi < 4; mi++)
#pragma unroll
                for (int ni = 0; ni < 8; ni++)
                    mma_tf32(acc[mi][ni], af[mi], bf[ni]);
        }
        // one barrier per kt: STS(kt+1) targets buf^1, last read in compute(kt-1),
        // ordered by the barrier above (same argument as validated R6 kernel).
    }

#pragma unroll
    for (int mi = 0; mi < 4; mi++) {
        int r = bm + mBase + mi * 16 + row4;
#pragma unroll
        for (int ni = 0; ni < 8; ni++) {
            int cb = bn + nBase + ni * 8 + 2 * col4;
            float2 b2 = make_float2(0.f, 0.f);
            if (bias) { b2.x = bias[cb]; b2.y = bias[cb + 1]; }
            float2 v0 = make_float2(acc[mi][ni][0] + b2.x, acc[mi][ni][1] + b2.y);
            float2 v1 = make_float2(acc[mi][ni][2] + b2.x, acc[mi][ni][3] + b2.y);
            *(float2*)(C + (size_t)r * N + cb) = v0;
            *(float2*)(C + (size_t)(r + 8) * N + cb) = v1;
        }
    }
}

// ---------------- residual add + RMSNorm ----------------
__global__ __launch_bounds__(256) void rmsnorm_kernel(
    float* __restrict__ y2, const float* __restrict__ x, const float* __restrict__ w)
{
    int m = blockIdx.x;
    float* yrow = y2 + (size_t)m * Hh;
    const float* xrow = x + (size_t)m * Hh;

    float ss = 0.f;
    for (int i = threadIdx.x; i < Hh; i += 256) {
        float t = yrow[i] + xrow[i];
        ss += t * t;
    }
#pragma unroll
    for (int off = 16; off > 0; off >>= 1)
        ss += __shfl_xor_sync(0xffffffffu, ss, off);

    __shared__ float red[9];
    int lane = threadIdx.x & 31, wid = threadIdx.x >> 5;
    if (lane == 0) red[wid] = ss;
    __syncthreads();
    if (threadIdx.x == 0) {
        float tot = 0.f;
        for (int i = 0; i < 8; i++) tot += red[i];
        red[8] = rsqrtf(tot / (float)Hh + EPSc);
    }
    __syncthreads();
    float inv = red[8];
    for (int i = threadIdx.x; i < Hh; i += 256) {
        float t = yrow[i] + xrow[i];
        yrow[i] = t * w[i] * inv;
    }
}

// ---------------- RoPE in place on qk buffer ----------------
__global__ __launch_bounds__(128) void rope_kernel(
    float* __restrict__ qkbuf, const float* __restrict__ freqs,
    const int* __restrict__ positions)
{
    int mh = blockIdx.x;
    int m = mh / NHh, h = mh % NHh;
    int pos = positions[m];
    int t = threadIdx.x;
    int isK = t >> 6;
    int d = t & 63;

    size_t base = (size_t)m * QKW + (size_t)h * 256 + (size_t)isK * 128;
    float f1 = freqs[(size_t)pos * HDd + d];
    float f2 = freqs[(size_t)pos * HDd + d + 64];
    float c1 = cosf(f1), s1 = sinf(f1);
    float c2 = cosf(f2), s2 = sinf(f2);
    float x1 = qkbuf[base + d];
    float x2 = qkbuf[base + d + 64];
    qkbuf[base + d]      = x1 * c1 - x2 * s1;
    qkbuf[base + d + 64] = x2 * c2 + x1 * s2;
}

// ---------------- tensor-core causal flash attention (mma.sync tf32) ----------------
#define FTQ 128
#define FTK 32
#define FPD 132
#define FPP 36
#define FQ_SZ (FTQ * FPD)
#define FK_SZ (FTK * FPD)
#define FP_SZ (FTQ * FPP)
#define FSMEM_BYTES ((2 * FQ_SZ + 3 * FK_SZ + FP_SZ) * 4)

__global__ __launch_bounds__(256, 1) void flash_tc_kernel(
    const float* __restrict__ qkbuf, const float* __restrict__ vbuf,
    float* __restrict__ attn)
{
    extern __shared__ uint32_t fsm[];
    uint32_t* Qhi = fsm;
    uint32_t* Qlo = Qhi + FQ_SZ;
    uint32_t* Khi = Qlo + FQ_SZ;
    uint32_t* Klo = Khi + FK_SZ;
    uint32_t* Vs  = Klo + FK_SZ;
    uint32_t* Ps  = Vs  + FK_SZ;

    const int qt = gridDim.x - 1 - blockIdx.x;
    const int h  = blockIdx.y;
    const int b  = blockIdx.z;
    const int q0 = qt * FTQ;
    const int tid  = threadIdx.x;
    const int lane = tid & 31;
    const int warp = tid >> 5;
    const int wm16 = warp * 16;
    const int row4 = lane >> 2;
    const int col4 = lane & 3;
    const int bS = b * Ss;
    const int hq = h * 256;
    const float scale = 0.08838834764831845f;

    for (int c = tid; c < FTQ * 32; c += 256) {
        int row = c >> 5, colf = (c & 31) << 2;
        float4 q4 = *(const float4*)(qkbuf + (size_t)(bS + q0 + row) * QKW + hq + colf);
        uint4 hi, lo; float x;
        x = q4.x * scale; hi.x = f2tf(x); lo.x = f2tf(x - __uint_as_float(hi.x));
        x = q4.y * scale; hi.y = f2tf(x); lo.y = f2tf(x - __uint_as_float(hi.y));
        x = q4.z * scale; hi.z = f2tf(x); lo.z = f2tf(x - __uint_as_float(hi.z));
        x = q4.w * scale; hi.w = f2tf(x); lo.w = f2tf(x - __uint_as_float(hi.w));
        *(uint4*)&Qhi[row * FPD + colf] = hi;
        *(uint4*)&Qlo[row * FPD + colf] = lo;
    }

    float O[16][4];
#pragma unroll
    for (int ni = 0; ni < 16; ni++)
#pragma unroll
        for (int e = 0; e < 4; e++) O[ni][e] = 0.f;
    float mrow0 = -1e30f, mrow1 = -1e30f, lrow0 = 0.f, lrow1 = 0.f;

    const int kend = q0 + FTQ;
    for (int j0 = 0; j0 < kend; j0 += FTK) {
        __syncthreads();
        for (int c = tid; c < FTK * 32; c += 256) {
            int row = c >> 5, colf = (c & 31) << 2;
            float4 k4 = *(const float4*)(qkbuf + (size_t)(bS + j0 + row) * QKW + hq + 128 + colf);
            uint4 hi, lo;
            hi.x = f2tf(k4.x); lo.x = f2tf(k4.x - __uint_as_float(hi.x));
            hi.y = f2tf(k4.y); lo.y = f2tf(k4.y - __uint_as_float(hi.y));
            hi.z = f2tf(k4.z); lo.z = f2tf(k4.z - __uint_as_float(hi.z));
            hi.w = f2tf(k4.w); lo.w = f2tf(k4.w - __uint_as_float(hi.w));
            *(uint4*)&Khi[row * FPD + colf] = hi;
            *(uint4*)&Klo[row * FPD + colf] = lo;
            float4 v4 = *(const float4*)(vbuf + (size_t)(bS + j0 + row) * Pp + h * HDd + colf);
            uint4 vv;
            vv.x = f2tf(v4.x); vv.y = f2tf(v4.y); vv.z = f2tf(v4.z); vv.w = f2tf(v4.w);
            *(uint4*)&Vs[row * FPD + colf] = vv;
        }
        __syncthreads();

        bool active = (j0 <= q0 + wm16 + 15);
        if (active) {
            float s[4][4];
#pragma unroll
            for (int ni = 0; ni < 4; ni++)
#pragma unroll
                for (int e = 0; e < 4; e++) s[ni][e] = 0.f;

#pragma unroll
            for (int kk = 0; kk < HDd; kk += 8) {
                int ra = (wm16 + row4) * FPD + kk + col4;
                int rb8 = ra + 8 * FPD;
                uint32_t ahi[4] = {Qhi[ra], Qhi[rb8], Qhi[ra + 4], Qhi[rb8 + 4]};
                uint32_t alo[4] = {Qlo[ra], Qlo[rb8], Qlo[ra + 4], Qlo[rb8 + 4]};
#pragma unroll
                for (int ni = 0; ni < 4; ni++) {
                    int rn = (ni * 8 + row4) * FPD + kk + col4;
                    uint32_t bh[2] = {Khi[rn], Khi[rn + 4]};
                    uint32_t bl[2] = {Klo[rn], Klo[rn + 4]};
                    mma_tf32(s[ni], ahi, bh);
                    mma_tf32(s[ni], alo, bh);
                    mma_tf32(s[ni], ahi, bl);
                }
            }

            if (j0 + FTK - 1 > q0 + wm16) {
                int qlo = q0 + wm16 + row4;
                int qhi = qlo + 8;
#pragma unroll
                for (int ni = 0; ni < 4; ni++) {
                    int kp = j0 + ni * 8 + 2 * col4;
                    if (kp     > qlo) s[ni][0] = -1e30f;
                    if (kp + 1 > qlo) s[ni][1] = -1e30f;
                    if (kp     > qhi) s[ni][2] = -1e30f;
                    if (kp + 1 > qhi) s[ni][3] = -1e30f;
                }
            }

            float mx0 = -1e30f, mx1 = -1e30f;
#pragma unroll
            for (int ni = 0; ni < 4; ni++) {
                mx0 = fmaxf(mx0, fmaxf(s[ni][0], s[ni][1]));
                mx1 = fmaxf(mx1, fmaxf(s[ni][2], s[ni][3]));
            }
            mx0 = fmaxf(mx0, __shfl_xor_sync(0xffffffffu, mx0, 1));
            mx0 = fmaxf(mx0, __shfl_xor_sync(0xffffffffu, mx0, 2));
            mx1 = fmaxf(mx1, __shfl_xor_sync(0xffffffffu, mx1, 1));
            mx1 = fmaxf(mx1, __shfl_xor_sync(0xffffffffu, mx1, 2));
            float mn0 = fmaxf(mrow0, mx0), mn1 = fmaxf(mrow1, mx1);
            float al0 = __expf(mrow0 - mn0), al1 = __expf(mrow1 - mn1);
            mrow0 = mn0; mrow1 = mn1;

            float sum0 = 0.f, sum1 = 0.f;
            int pbase = (wm16 + row4) * FPP + 2 * col4;
#pragma unroll
            for (int ni = 0; ni < 4; ni++) {
                float p0 = __expf(s[ni][0] - mn0);
                float p1 = __expf(s[ni][1] - mn0);
                float p2 = __expf(s[ni][2] - mn1);
                float p3 = __expf(s[ni][3] - mn1);
                sum0 += p0 + p1; sum1 += p2 + p3;
                Ps[pbase + ni * 8]               = f2tf(p0);
                Ps[pbase + ni * 8 + 1]           = f2tf(p1);
                Ps[pbase + ni * 8 + 8 * FPP]     = f2tf(p2);
                Ps[pbase + ni * 8 + 8 * FPP + 1] = f2tf(p3);
            }
            lrow0 = lrow0 * al0 + sum0;
            lrow1 = lrow1 * al1 + sum1;
#pragma unroll
            for (int ni = 0; ni < 16; ni++) {
                O[ni][0] *= al0; O[ni][1] *= al0;
                O[ni][2] *= al1; O[ni][3] *= al1;
            }
            __syncwarp();

#pragma unroll
            for (int kp = 0; kp < FTK; kp += 8) {
                int pa = (wm16 + row4) * FPP + kp + col4;
                uint32_t a[4] = {Ps[pa], Ps[pa + 8 * FPP], Ps[pa + 4], Ps[pa + 8 * FPP + 4]};
#pragma unroll
                for (int ni = 0; ni < 16; ni++) {
                    int vb = (kp + col4) * FPD + ni * 8 + row4;
                    uint32_t bv[2] = {Vs[vb], Vs[vb + 4 * FPD]};
                    mma_tf32(O[ni], a, bv);
                }
            }
        }
    }

    lrow0 += __shfl_xor_sync(0xffffffffu, lrow0, 1);
    lrow0 += __shfl_xor_sync(0xffffffffu, lrow0, 2);
    lrow1 += __shfl_xor_sync(0xffffffffu, lrow1, 1);
    lrow1 += __shfl_xor_sync(0xffffffffu, lrow1, 2);
    float inv0 = 1.f / lrow0, inv1 = 1.f / lrow1;

    size_t ob0 = (size_t)(bS + q0 + wm16 + row4) * Pp + h * HDd;
    size_t ob1 = ob0 + (size_t)8 * Pp;
#pragma unroll
    for (int ni = 0; ni < 16; ni++) {
        int cb = ni * 8 + 2 * col4;
        *(float2*)(attn + ob0 + cb) = make_float2(O[ni][0] * inv0, O[ni][1] * inv0);
        *(float2*)(attn + ob1 + cb) = make_float2(O[ni][2] * inv1, O[ni][3] * inv1);
    }
}

// ---------------- tail outputs ----------------
__global__ void tails_kernel(const float* __restrict__ hs, const float* __restrict__ y1,
                             float* __restrict__ out)
{
    int i = blockIdx.x * 256 + threadIdx.x;
    size_t off1 = (size_t)Mm * Hh;
    size_t off2 = off1 + (size_t)Bb * Hh;
    if (i < Bb * Hh) {
        int b = i / Hh, hh = i % Hh;
        out[off1 + i] = hs[((size_t)b * Ss + (Ss - 1)) * Hh + hh];
    }
    if (i < Bb * H2) {
        int b = i / H2, oo = i % H2;
        out[off2 + i] = y1[((size_t)b * Ss + (Ss - 1)) * H2 + oo];
    }
}

// ---------------- launch ----------------
extern "C" void kernel_launch(void* const* d_in, const int* in_sizes, int n_in,
                              void* d_out, int out_size)
{
    (void)in_sizes; (void)n_in; (void)out_size;
    const float* hs      = (const float*)d_in[0];
    const float* freqs   = (const float*)d_in[1];
    const int*   pos     = (const int*)  d_in[2];
    const float* Wqk     = (const float*)d_in[3];
    const float* Wv      = (const float*)d_in[4];
    const float* Wo      = (const float*)d_in[5];
    const float* conv1_w = (const float*)d_in[6];
    const float* conv1_b = (const float*)d_in[7];
    const float* conv2_w = (const float*)d_in[8];
    const float* conv2_b = (const float*)d_in[9];
    const float* ln_w    = (const float*)d_in[10];
    const float* lf1c    = (const float*)d_in[11];
    const float* lf2c    = (const float*)d_in[12];
    float* out = (float*)d_out;

    float *v, *xprev, *y1, *y1prev, *lfout, *qk, *attn;
    float *w1a, *w1b, *w2a, *w2b;
    cudaGetSymbolAddress((void**)&v,      g_v);
    cudaGetSymbolAddress((void**)&xprev,  g_xprev);
    cudaGetSymbolAddress((void**)&y1,     g_y1);
    cudaGetSymbolAddress((void**)&y1prev, g_y1prev);
    cudaGetSymbolAddress((void**)&lfout,  g_lfout);
    cudaGetSymbolAddress((void**)&qk,     g_qk);
    cudaGetSymbolAddress((void**)&attn,   g_attn);
    cudaGetSymbolAddress((void**)&w1a,    g_w1a);
    cudaGetSymbolAddress((void**)&w1b,    g_w1b);
    cudaGetSymbolAddress((void**)&w2a,    g_w2a);
    cudaGetSymbolAddress((void**)&w2b,    g_w2b);

    static bool attr_done = false;
    if (!attr_done) {
        cudaFuncSetAttribute(flash_tc_kernel,
                             cudaFuncAttributeMaxDynamicSharedMemorySize, FSMEM_BYTES);
        cudaFuncSetAttribute(gemm_v2_kernel,
                             cudaFuncAttributeMaxDynamicSharedMemorySize, G2_SMEM);
        attr_done = true;
    }

    // 1) deinterleave conv weights
    {
        int n1 = H2 * Hh;
        deint_kernel<<<(n1 + 255) / 256, 256>>>(conv1_w, w1a, w1b, n1);
        int n2 = Hh * H2;
        deint_kernel<<<(n2 + 255) / 256, 256>>>(conv2_w, w2a, w2b, n2);
    }

    // 2) shifted hidden
    shift_kernel<<<Mm, 256>>>(hs, lf1c, xprev, Hh);

    // 3) v = hs @ Wv^T
    gemm_v2_kernel<<<dim3(Pp / BN2, Mm / BM2), 256, G2_SMEM>>>(
        hs, Wv, nullptr, nullptr, v, Pp, Hh, nullptr);

    // 4) y1 = xprev @ w1a^T + hs @ w1b^T + b1  (fused dual-K)
    gemm_v2_kernel<<<dim3(H2 / BN2, Mm / BM2), 256, G2_SMEM>>>(
        xprev, w1a, hs, w1b, y1, H2, Hh, conv1_b);

    // 5) shifted y1
    shift_kernel<<<Mm, 256>>>(y1, lf2c, y1prev, H2);

    // 6) y2 = y1prev @ w2a^T + y1 @ w2b^T + b2  (fused dual-K)
    gemm_v2_kernel<<<dim3(Hh / BN2, Mm / BM2), 256, G2_SMEM>>>(
        y1prev, w2a, y1, w2b, lfout, Hh, H2, conv2_b);

    // 7) lf_out = rmsnorm(y2 + hs) * ln_w
    rmsnorm_kernel<<<Mm, 256>>>(lfout, hs, ln_w);

    // 8) qk = lf_out @ Wqk^T
    gemm_v2_kernel<<<dim3(QKW / BN2, Mm / BM2), 256, G2_SMEM>>>(
        lfout, Wqk, nullptr, nullptr, qk, QKW, Hh, nullptr);

    // 9) RoPE in place
    rope_kernel<<<Mm * NHh, 128>>>(qk, freqs, pos);

    // 10) tensor-core causal flash attention
    flash_tc_kernel<<<dim3(Ss / FTQ, NHh, Bb), 256, FSMEM_BYTES>>>(qk, v, attn);

    // 11) output = attn @ Wo^T
    gemm_v2_kernel<<<dim3(Hh / BN2, Mm / BM2), 256, G2_SMEM>>>(
        attn, Wo, nullptr, nullptr, out, Hh, Pp, nullptr);

    // 12) tails
    tails_kernel<<<(Bb * Hh + 255) / 256, 256>>>(hs, y1, out);
}

// round 9
// speedup vs baseline: 1.0338x; 1.0338x over previous
#include <cuda_runtime.h>
#include <cuda_bf16.h>
#include <cstdint>
#include <cstddef>

// Problem constants
#define Bb   2
#define Ss   2048
#define Hh   2048
#define NHh  16
#define HDd  128
#define Pp   2048
#define Mm   (Bb * Ss)          // 4096 rows
#define H2   (Hh / 2)           // 1024
#define QKW  (2 * Pp)           // 4096 (qk row width)
#define EPSc 1e-6f

// ---------------- scratch (static device globals; no allocation) ----------------
__device__ float g_v[(size_t)Mm * Pp];
__device__ float g_xprev[(size_t)Mm * Hh];
__device__ float g_y1[(size_t)Mm * H2];
__device__ float g_y1prev[(size_t)Mm * H2];
__device__ float g_lfout[(size_t)Mm * Hh];
__device__ float g_qk[(size_t)Mm * QKW];
__device__ float g_attn[(size_t)Mm * Pp];
__device__ float g_w1a[(size_t)H2 * Hh];
__device__ float g_w1b[(size_t)H2 * Hh];
__device__ float g_w2a[(size_t)Hh * H2];
__device__ float g_w2b[(size_t)Hh * H2];

// ---------------- helpers ----------------
__device__ __forceinline__ uint32_t f2tf(float x) {
    uint32_t r;
    asm("cvt.rna.tf32.f32 %0, %1;" : "=r"(r) : "f"(x));
    return r;
}

__device__ __forceinline__ void mma_tf32(float* d, const uint32_t* a, const uint32_t* b) {
    asm volatile(
        "mma.sync.aligned.m16n8k8.row.col.f32.tf32.tf32.f32 "
        "{%0,%1,%2,%3},{%4,%5,%6,%7},{%8,%9},{%0,%1,%2,%3};"
        : "+f"(d[0]), "+f"(d[1]), "+f"(d[2]), "+f"(d[3])
        : "r"(a[0]), "r"(a[1]), "r"(a[2]), "r"(a[3]), "r"(b[0]), "r"(b[1]));
}

__device__ __forceinline__ void sts_cvt(uint32_t* p, float4 v) {
    uint4 u;
    u.x = f2tf(v.x); u.y = f2tf(v.y); u.z = f2tf(v.z); u.w = f2tf(v.w);
    *(uint4*)p = u;
}

// ---------------- deinterleave conv weights ----------------
__global__ void deint_kernel(const float* __restrict__ in, float* __restrict__ a,
                             float* __restrict__ b, int n)
{
    int i = blockIdx.x * 256 + threadIdx.x;
    if (i < n) {
        a[i] = in[2 * i];
        b[i] = in[2 * i + 1];
    }
}

// ---------------- shift rows by one seq step ----------------
__global__ void shift_kernel(const float* __restrict__ x, const float* __restrict__ cache,
                             float* __restrict__ out, int width)
{
    int m = blockIdx.x;
    int s = m % Ss;
    int b = m / Ss;
    const float* src = (s == 0) ? (cache + (size_t)b * width)
                                : (x + (size_t)(m - 1) * width);
    float* dst = out + (size_t)m * width;
    for (int i = threadIdx.x; i < width; i += 256) dst[i] = src[i];
}

// ========== TF32 tensor-core GEMM v3 (NT), 128x64 block, warp tile 32x32 ==========
// Occupancy-first: 3 CTAs/SM (launch_bounds), small acc footprint, double buffer.
// C[M,N] = A[M,K] * W[N,K]^T (+ A2[M,K] * W2[N,K]^T) (+bias)
// 8 warps (4x2), BK=16.  M%128==0, N%64==0, K%16==0.
#define BM3 128
#define BN3 64
#define BK3 16
#define PAD3 20

__global__ __launch_bounds__(256, 3) void gemm_v3_kernel(
    const float* __restrict__ A, const float* __restrict__ W,
    const float* __restrict__ A2, const float* __restrict__ W2,
    float* __restrict__ C, int N, int K, const float* __restrict__ bias)
{
    __shared__ uint32_t As[2][BM3 * PAD3];   // 2 x 2560 words
    __shared__ uint32_t Bs[2][BN3 * PAD3];   // 2 x 1280 words  (total 30 KB)

    const int tid = threadIdx.x;
    const int lane = tid & 31;
    const int warp = tid >> 5;
    const int wm = warp >> 1;           // 0..3  (32 rows each)
    const int wn = warp & 1;            // 0..1  (32 cols each)
    const int bm = blockIdx.y * BM3;
    const int bn = blockIdx.x * BN3;
    const int mBase = wm * 32;
    const int nBase = wn * 32;

    // staging coords: A rows rs and rs+64 (2 chunks), B row rs (1 chunk)
    const int rs = tid >> 2;            // 0..63
    const int cs = (tid & 3) << 2;      // 0,4,8,12

    float acc[2][4][4];
#pragma unroll
    for (int mi = 0; mi < 2; mi++)
#pragma unroll
        for (int ni = 0; ni < 4; ni++)
#pragma unroll
            for (int e = 0; e < 4; e++) acc[mi][ni][e] = 0.f;

    const int nk = K / BK3;
    const int nkt = A2 ? (2 * nk) : nk;

    // prefetch kt = 0
    float4 pa0 = *(const float4*)(A + (size_t)(bm + rs) * K + cs);
    float4 pa1 = *(const float4*)(A + (size_t)(bm + rs + 64) * K + cs);
    float4 pb0 = *(const float4*)(W + (size_t)(bn + rs) * K + cs);

    const int row4 = lane >> 2;
    const int col4 = lane & 3;

    for (int kt = 0; kt < nkt; kt++) {
        int buf = kt & 1;
        uint32_t* as = As[buf];
        uint32_t* bs = Bs[buf];
        sts_cvt(&as[rs * PAD3 + cs], pa0);
        sts_cvt(&as[(rs + 64) * PAD3 + cs], pa1);
        sts_cvt(&bs[rs * PAD3 + cs], pb0);
        __syncthreads();

        if (kt + 1 < nkt) {
            int k2 = kt + 1;
            const float* Ap; const float* Wp; int ko;
            if (k2 < nk) { Ap = A;  Wp = W;  ko = k2 * BK3; }
            else         { Ap = A2; Wp = W2; ko = (k2 - nk) * BK3; }
            pa0 = *(const float4*)(Ap + (size_t)(bm + rs) * K + ko + cs);
            pa1 = *(const float4*)(Ap + (size_t)(bm + rs + 64) * K + ko + cs);
            pb0 = *(const float4*)(Wp + (size_t)(bn + rs) * K + ko + cs);
        }

#pragma unroll
        for (int kk = 0; kk < BK3; kk += 8) {
            uint32_t af[2][4], bf[4][2];
#pragma unroll
            for (int mi = 0; mi < 2; mi++) {
                int m0 = mBase + mi * 16;
                af[mi][0] = as[(m0 + row4) * PAD3 + kk + col4];
                af[mi][1] = as[(m0 + row4 + 8) * PAD3 + kk + col4];
                af[mi][2] = as[(m0 + row4) * PAD3 + kk + col4 + 4];
                af[mi][3] = as[(m0 + row4 + 8) * PAD3 + kk + col4 + 4];
            }
#pragma unroll
            for (int ni = 0; ni < 4; ni++) {
                int n0 = nBase + ni * 8;
                bf[ni][0] = bs[(n0 + row4) * PAD3 + kk + col4];
                bf[ni][1] = bs[(n0 + row4) * PAD3 + kk + col4 + 4];
            }
#pragma unroll
            for (int mi = 0; mi < 2; mi++)
#pragma unroll
                for (int ni = 0; ni < 4; ni++)
                    mma_tf32(acc[mi][ni], af[mi], bf[ni]);
        }
        // one barrier per kt: STS(kt+1) targets buf^1, last read in compute(kt-1),
        // ordered by the barrier above (same argument as validated R6 kernel).
    }

#pragma unroll
    for (int mi = 0; mi < 2; mi++) {
        int r = bm + mBase + mi * 16 + row4;
#pragma unroll
        for (int ni = 0; ni < 4; ni++) {
            int cb = bn + nBase + ni * 8 + 2 * col4;
            float2 b2 = make_float2(0.f, 0.f);
            if (bias) { b2.x = bias[cb]; b2.y = bias[cb + 1]; }
            float2 v0 = make_float2(acc[mi][ni][0] + b2.x, acc[mi][ni][1] + b2.y);
            float2 v1 = make_float2(acc[mi][ni][2] + b2.x, acc[mi][ni][3] + b2.y);
            *(float2*)(C + (size_t)r * N + cb) = v0;
            *(float2*)(C + (size_t)(r + 8) * N + cb) = v1;
        }
    }
}

// ---------------- residual add + RMSNorm ----------------
__global__ __launch_bounds__(256) void rmsnorm_kernel(
    float* __restrict__ y2, const float* __restrict__ x, const float* __restrict__ w)
{
    int m = blockIdx.x;
    float* yrow = y2 + (size_t)m * Hh;
    const float* xrow = x + (size_t)m * Hh;

    float ss = 0.f;
    for (int i = threadIdx.x; i < Hh; i += 256) {
        float t = yrow[i] + xrow[i];
        ss += t * t;
    }
#pragma unroll
    for (int off = 16; off > 0; off >>= 1)
        ss += __shfl_xor_sync(0xffffffffu, ss, off);

    __shared__ float red[9];
    int lane = threadIdx.x & 31, wid = threadIdx.x >> 5;
    if (lane == 0) red[wid] = ss;
    __syncthreads();
    if (threadIdx.x == 0) {
        float tot = 0.f;
        for (int i = 0; i < 8; i++) tot += red[i];
        red[8] = rsqrtf(tot / (float)Hh + EPSc);
    }
    __syncthreads();
    float inv = red[8];
    for (int i = threadIdx.x; i < Hh; i += 256) {
        float t = yrow[i] + xrow[i];
        yrow[i] = t * w[i] * inv;
    }
}

// ---------------- RoPE in place on qk buffer ----------------
__global__ __launch_bounds__(128) void rope_kernel(
    float* __restrict__ qkbuf, const float* __restrict__ freqs,
    const int* __restrict__ positions)
{
    int mh = blockIdx.x;
    int m = mh / NHh, h = mh % NHh;
    int pos = positions[m];
    int t = threadIdx.x;
    int isK = t >> 6;
    int d = t & 63;

    size_t base = (size_t)m * QKW + (size_t)h * 256 + (size_t)isK * 128;
    float f1 = freqs[(size_t)pos * HDd + d];
    float f2 = freqs[(size_t)pos * HDd + d + 64];
    float c1 = cosf(f1), s1 = sinf(f1);
    float c2 = cosf(f2), s2 = sinf(f2);
    float x1 = qkbuf[base + d];
    float x2 = qkbuf[base + d + 64];
    qkbuf[base + d]      = x1 * c1 - x2 * s1;
    qkbuf[base + d + 64] = x2 * c2 + x1 * s2;
}

// ---------------- tensor-core causal flash attention (mma.sync tf32) ----------------
#define FTQ 128
#define FTK 32
#define FPD 132
#define FPP 36
#define FQ_SZ (FTQ * FPD)
#define FK_SZ (FTK * FPD)
#define FP_SZ (FTQ * FPP)
#define FSMEM_BYTES ((2 * FQ_SZ + 3 * FK_SZ + FP_SZ) * 4)

__global__ __launch_bounds__(256, 1) void flash_tc_kernel(
    const float* __restrict__ qkbuf, const float* __restrict__ vbuf,
    float* __restrict__ attn)
{
    extern __shared__ uint32_t fsm[];
    uint32_t* Qhi = fsm;
    uint32_t* Qlo = Qhi + FQ_SZ;
    uint32_t* Khi = Qlo + FQ_SZ;
    uint32_t* Klo = Khi + FK_SZ;
    uint32_t* Vs  = Klo + FK_SZ;
    uint32_t* Ps  = Vs  + FK_SZ;

    const int qt = gridDim.x - 1 - blockIdx.x;
    const int h  = blockIdx.y;
    const int b  = blockIdx.z;
    const int q0 = qt * FTQ;
    const int tid  = threadIdx.x;
    const int lane = tid & 31;
    const int warp = tid >> 5;
    const int wm16 = warp * 16;
    const int row4 = lane >> 2;
    const int col4 = lane & 3;
    const int bS = b * Ss;
    const int hq = h * 256;
    const float scale = 0.08838834764831845f;

    for (int c = tid; c < FTQ * 32; c += 256) {
        int row = c >> 5, colf = (c & 31) << 2;
        float4 q4 = *(const float4*)(qkbuf + (size_t)(bS + q0 + row) * QKW + hq + colf);
        uint4 hi, lo; float x;
        x = q4.x * scale; hi.x = f2tf(x); lo.x = f2tf(x - __uint_as_float(hi.x));
        x = q4.y * scale; hi.y = f2tf(x); lo.y = f2tf(x - __uint_as_float(hi.y));
        x = q4.z * scale; hi.z = f2tf(x); lo.z = f2tf(x - __uint_as_float(hi.z));
        x = q4.w * scale; hi.w = f2tf(x); lo.w = f2tf(x - __uint_as_float(hi.w));
        *(uint4*)&Qhi[row * FPD + colf] = hi;
        *(uint4*)&Qlo[row * FPD + colf] = lo;
    }

    float O[16][4];
#pragma unroll
    for (int ni = 0; ni < 16; ni++)
#pragma unroll
        for (int e = 0; e < 4; e++) O[ni][e] = 0.f;
    float mrow0 = -1e30f, mrow1 = -1e30f, lrow0 = 0.f, lrow1 = 0.f;

    const int kend = q0 + FTQ;
    for (int j0 = 0; j0 < kend; j0 += FTK) {
        __syncthreads();
        for (int c = tid; c < FTK * 32; c += 256) {
            int row = c >> 5, colf = (c & 31) << 2;
            float4 k4 = *(const float4*)(qkbuf + (size_t)(bS + j0 + row) * QKW + hq + 128 + colf);
            uint4 hi, lo;
            hi.x = f2tf(k4.x); lo.x = f2tf(k4.x - __uint_as_float(hi.x));
            hi.y = f2tf(k4.y); lo.y = f2tf(k4.y - __uint_as_float(hi.y));
            hi.z = f2tf(k4.z); lo.z = f2tf(k4.z - __uint_as_float(hi.z));
            hi.w = f2tf(k4.w); lo.w = f2tf(k4.w - __uint_as_float(hi.w));
            *(uint4*)&Khi[row * FPD + colf] = hi;
            *(uint4*)&Klo[row * FPD + colf] = lo;
            float4 v4 = *(const float4*)(vbuf + (size_t)(bS + j0 + row) * Pp + h * HDd + colf);
            uint4 vv;
            vv.x = f2tf(v4.x); vv.y = f2tf(v4.y); vv.z = f2tf(v4.z); vv.w = f2tf(v4.w);
            *(uint4*)&Vs[row * FPD + colf] = vv;
        }
        __syncthreads();

        bool active = (j0 <= q0 + wm16 + 15);
        if (active) {
            float s[4][4];
#pragma unroll
            for (int ni = 0; ni < 4; ni++)
#pragma unroll
                for (int e = 0; e < 4; e++) s[ni][e] = 0.f;

#pragma unroll
            for (int kk = 0; kk < HDd; kk += 8) {
                int ra = (wm16 + row4) * FPD + kk + col4;
                int rb8 = ra + 8 * FPD;
                uint32_t ahi[4] = {Qhi[ra], Qhi[rb8], Qhi[ra + 4], Qhi[rb8 + 4]};
                uint32_t alo[4] = {Qlo[ra], Qlo[rb8], Qlo[ra + 4], Qlo[rb8 + 4]};
#pragma unroll
                for (int ni = 0; ni < 4; ni++) {
                    int rn = (ni * 8 + row4) * FPD + kk + col4;
                    uint32_t bh[2] = {Khi[rn], Khi[rn + 4]};
                    uint32_t bl[2] = {Klo[rn], Klo[rn + 4]};
                    mma_tf32(s[ni], ahi, bh);
                    mma_tf32(s[ni], alo, bh);
                    mma_tf32(s[ni], ahi, bl);
                }
            }

            if (j0 + FTK - 1 > q0 + wm16) {
                int qlo = q0 + wm16 + row4;
                int qhi = qlo + 8;
#pragma unroll
                for (int ni = 0; ni < 4; ni++) {
                    int kp = j0 + ni * 8 + 2 * col4;
                    if (kp     > qlo) s[ni][0] = -1e30f;
                    if (kp + 1 > qlo) s[ni][1] = -1e30f;
                    if (kp     > qhi) s[ni][2] = -1e30f;
                    if (kp + 1 > qhi) s[ni][3] = -1e30f;
                }
            }

            float mx0 = -1e30f, mx1 = -1e30f;
#pragma unroll
            for (int ni = 0; ni < 4; ni++) {
                mx0 = fmaxf(mx0, fmaxf(s[ni][0], s[ni][1]));
                mx1 = fmaxf(mx1, fmaxf(s[ni][2], s[ni][3]));
            }
            mx0 = fmaxf(mx0, __shfl_xor_sync(0xffffffffu, mx0, 1));
            mx0 = fmaxf(mx0, __shfl_xor_sync(0xffffffffu, mx0, 2));
            mx1 = fmaxf(mx1, __shfl_xor_sync(0xffffffffu, mx1, 1));
            mx1 = fmaxf(mx1, __shfl_xor_sync(0xffffffffu, mx1, 2));
            float mn0 = fmaxf(mrow0, mx0), mn1 = fmaxf(mrow1, mx1);
            float al0 = __expf(mrow0 - mn0), al1 = __expf(mrow1 - mn1);
            mrow0 = mn0; mrow1 = mn1;

            float sum0 = 0.f, sum1 = 0.f;
            int pbase = (wm16 + row4) * FPP + 2 * col4;
#pragma unroll
            for (int ni = 0; ni < 4; ni++) {
                float p0 = __expf(s[ni][0] - mn0);
                float p1 = __expf(s[ni][1] - mn0);
                float p2 = __expf(s[ni][2] - mn1);
                float p3 = __expf(s[ni][3] - mn1);
                sum0 += p0 + p1; sum1 += p2 + p3;
                Ps[pbase + ni * 8]               = f2tf(p0);
                Ps[pbase + ni * 8 + 1]           = f2tf(p1);
                Ps[pbase + ni * 8 + 8 * FPP]     = f2tf(p2);
                Ps[pbase + ni * 8 + 8 * FPP + 1] = f2tf(p3);
            }
            lrow0 = lrow0 * al0 + sum0;
            lrow1 = lrow1 * al1 + sum1;
#pragma unroll
            for (int ni = 0; ni < 16; ni++) {
                O[ni][0] *= al0; O[ni][1] *= al0;
                O[ni][2] *= al1; O[ni][3] *= al1;
            }
            __syncwarp();

#pragma unroll
            for (int kp = 0; kp < FTK; kp += 8) {
                int pa = (wm16 + row4) * FPP + kp + col4;
                uint32_t a[4] = {Ps[pa], Ps[pa + 8 * FPP], Ps[pa + 4], Ps[pa + 8 * FPP + 4]};
#pragma unroll
                for (int ni = 0; ni < 16; ni++) {
                    int vb = (kp + col4) * FPD + ni * 8 + row4;
                    uint32_t bv[2] = {Vs[vb], Vs[vb + 4 * FPD]};
                    mma_tf32(O[ni], a, bv);
                }
            }
        }
    }

    lrow0 += __shfl_xor_sync(0xffffffffu, lrow0, 1);
    lrow0 += __shfl_xor_sync(0xffffffffu, lrow0, 2);
    lrow1 += __shfl_xor_sync(0xffffffffu, lrow1, 1);
    lrow1 += __shfl_xor_sync(0xffffffffu, lrow1, 2);
    float inv0 = 1.f / lrow0, inv1 = 1.f / lrow1;

    size_t ob0 = (size_t)(bS + q0 + wm16 + row4) * Pp + h * HDd;
    size_t ob1 = ob0 + (size_t)8 * Pp;
#pragma unroll
    for (int ni = 0; ni < 16; ni++) {
        int cb = ni * 8 + 2 * col4;
        *(float2*)(attn + ob0 + cb) = make_float2(O[ni][0] * inv0, O[ni][1] * inv0);
        *(float2*)(attn + ob1 + cb) = make_float2(O[ni][2] * inv1, O[ni][3] * inv1);
    }
}

// ---------------- tail outputs ----------------
__global__ void tails_kernel(const float* __restrict__ hs, const float* __restrict__ y1,
                             float* __restrict__ out)
{
    int i = blockIdx.x * 256 + threadIdx.x;
    size_t off1 = (size_t)Mm * Hh;
    size_t off2 = off1 + (size_t)Bb * Hh;
    if (i < Bb * Hh) {
        int b = i / Hh, hh = i % Hh;
        out[off1 + i] = hs[((size_t)b * Ss + (Ss - 1)) * Hh + hh];
    }
    if (i < Bb * H2) {
        int b = i / H2, oo = i % H2;
        out[off2 + i] = y1[((size_t)b * Ss + (Ss - 1)) * H2 + oo];
    }
}

// ---------------- launch ----------------
extern "C" void kernel_launch(void* const* d_in, const int* in_sizes, int n_in,
                              void* d_out, int out_size)
{
    (void)in_sizes; (void)n_in; (void)out_size;
    const float* hs      = (const float*)d_in[0];
    const float* freqs   = (const float*)d_in[1];
    const int*   pos     = (const int*)  d_in[2];
    const float* Wqk     = (const float*)d_in[3];
    const float* Wv      = (const float*)d_in[4];
    const float* Wo      = (const float*)d_in[5];
    const float* conv1_w = (const float*)d_in[6];
    const float* conv1_b = (const float*)d_in[7];
    const float* conv2_w = (const float*)d_in[8];
    const float* conv2_b = (const float*)d_in[9];
    const float* ln_w    = (const float*)d_in[10];
    const float* lf1c    = (const float*)d_in[11];
    const float* lf2c    = (const float*)d_in[12];
    float* out = (float*)d_out;

    float *v, *xprev, *y1, *y1prev, *lfout, *qk, *attn;
    float *w1a, *w1b, *w2a, *w2b;
    cudaGetSymbolAddress((void**)&v,      g_v);
    cudaGetSymbolAddress((void**)&xprev,  g_xprev);
    cudaGetSymbolAddress((void**)&y1,     g_y1);
    cudaGetSymbolAddress((void**)&y1prev, g_y1prev);
    cudaGetSymbolAddress((void**)&lfout,  g_lfout);
    cudaGetSymbolAddress((void**)&qk,     g_qk);
    cudaGetSymbolAddress((void**)&attn,   g_attn);
    cudaGetSymbolAddress((void**)&w1a,    g_w1a);
    cudaGetSymbolAddress((void**)&w1b,    g_w1b);
    cudaGetSymbolAddress((void**)&w2a,    g_w2a);
    cudaGetSymbolAddress((void**)&w2b,    g_w2b);

    static bool attr_done = false;
    if (!attr_done) {
        cudaFuncSetAttribute(flash_tc_kernel,
                             cudaFuncAttributeMaxDynamicSharedMemorySize, FSMEM_BYTES);
        attr_done = true;
    }

    // 1) deinterleave conv weights
    {
        int n1 = H2 * Hh;
        deint_kernel<<<(n1 + 255) / 256, 256>>>(conv1_w, w1a, w1b, n1);
        int n2 = Hh * H2;
        deint_kernel<<<(n2 + 255) / 256, 256>>>(conv2_w, w2a, w2b, n2);
    }

    // 2) shifted hidden
    shift_kernel<<<Mm, 256>>>(hs, lf1c, xprev, Hh);

    // 3) v = hs @ Wv^T
    gemm_v3_kernel<<<dim3(Pp / BN3, Mm / BM3), 256>>>(
        hs, Wv, nullptr, nullptr, v, Pp, Hh, nullptr);

    // 4) y1 = xprev @ w1a^T + hs @ w1b^T + b1  (fused dual-K)
    gemm_v3_kernel<<<dim3(H2 / BN3, Mm / BM3), 256>>>(
        xprev, w1a, hs, w1b, y1, H2, Hh, conv1_b);

    // 5) shifted y1
    shift_kernel<<<Mm, 256>>>(y1, lf2c, y1prev, H2);

    // 6) y2 = y1prev @ w2a^T + y1 @ w2b^T + b2  (fused dual-K)
    gemm_v3_kernel<<<dim3(Hh / BN3, Mm / BM3), 256>>>(
        y1prev, w2a, y1, w2b, lfout, Hh, H2, conv2_b);

    // 7) lf_out = rmsnorm(y2 + hs) * ln_w
    rmsnorm_kernel<<<Mm, 256>>>(lfout, hs, ln_w);

    // 8) qk = lf_out @ Wqk^T
    gemm_v3_kernel<<<dim3(QKW / BN3, Mm / BM3), 256>>>(
        lfout, Wqk, nullptr, nullptr, qk, QKW, Hh, nullptr);

    // 9) RoPE in place
    rope_kernel<<<Mm * NHh, 128>>>(qk, freqs, pos);

    // 10) tensor-core causal flash attention
    flash_tc_kernel<<<dim3(Ss / FTQ, NHh, Bb), 256, FSMEM_BYTES>>>(qk, v, attn);

    // 11) output = attn @ Wo^T
    gemm_v3_kernel<<<dim3(Hh / BN3, Mm / BM3), 256>>>(
        attn, Wo, nullptr, nullptr, out, Hh, Pp, nullptr);

    // 12) tails
    tails_kernel<<<(Bb * Hh + 255) / 256, 256>>>(hs, y1, out);
}

// round 10
// speedup vs baseline: 1.1588x; 1.1208x over previous
#include <cuda_runtime.h>
#include <cuda_bf16.h>
#include <cstdint>
#include <cstddef>

// Problem constants
#define Bb   2
#define Ss   2048
#define Hh   2048
#define NHh  16
#define HDd  128
#define Pp   2048
#define Mm   (Bb * Ss)          // 4096 rows
#define H2   (Hh / 2)           // 1024
#define QKW  (2 * Pp)           // 4096 (qk row width)
#define EPSc 1e-6f

// ---------------- scratch (static device globals; no allocation) ----------------
__device__ float g_v[(size_t)Mm * Pp];
__device__ float g_y1[(size_t)Mm * H2];
__device__ float g_lfout[(size_t)Mm * Hh];
__device__ float g_qk[(size_t)Mm * QKW];
__device__ float g_attn[(size_t)Mm * Pp];
__device__ float g_w1a[(size_t)H2 * Hh];
__device__ float g_w1b[(size_t)H2 * Hh];
__device__ float g_w2a[(size_t)Hh * H2];
__device__ float g_w2b[(size_t)Hh * H2];

// ---------------- helpers ----------------
__device__ __forceinline__ uint32_t f2tf(float x) {
    uint32_t r;
    asm("cvt.rna.tf32.f32 %0, %1;" : "=r"(r) : "f"(x));
    return r;
}

__device__ __forceinline__ void mma_tf32(float* d, const uint32_t* a, const uint32_t* b) {
    asm volatile(
        "mma.sync.aligned.m16n8k8.row.col.f32.tf32.tf32.f32 "
        "{%0,%1,%2,%3},{%4,%5,%6,%7},{%8,%9},{%0,%1,%2,%3};"
        : "+f"(d[0]), "+f"(d[1]), "+f"(d[2]), "+f"(d[3])
        : "r"(a[0]), "r"(a[1]), "r"(a[2]), "r"(a[3]), "r"(b[0]), "r"(b[1]));
}

__device__ __forceinline__ void sts_cvt(uint32_t* p, float4 v) {
    uint4 u;
    u.x = f2tf(v.x); u.y = f2tf(v.y); u.z = f2tf(v.z); u.w = f2tf(v.w);
    *(uint4*)p = u;
}

// ---------------- deinterleave conv weights ----------------
__global__ void deint_kernel(const float* __restrict__ in, float* __restrict__ a,
                             float* __restrict__ b, int n)
{
    int i = blockIdx.x * 256 + threadIdx.x;
    if (i < n) {
        a[i] = in[2 * i];
        b[i] = in[2 * i + 1];
    }
}

// ---------------- TF32 tensor-core GEMM (NT), convert-on-stage, optional dual-K ----------------
// C[M,N] = A1shift[M,K] * W[N,K]^T (+ A2[M,K] * W2[N,K]^T) (+bias)
// If shiftCache != nullptr, segment-1 A-rows are the one-step-shifted view of A:
//   row m reads A[m-1] (or shiftCache[m/Ss] when m%Ss==0).  Segment 2 reads A2 unshifted.
// 128x128 block, BK=16, 256 threads = 8 warps (2x4), warp tile 64x32.  (R6-validated layout.)
#define BMg 128
#define BNg 128
#define BKg 16
#define PADg 20

__global__ __launch_bounds__(256) void gemm_tf32_kernel(
    const float* __restrict__ A, const float* __restrict__ W,
    const float* __restrict__ A2, const float* __restrict__ W2,
    float* __restrict__ C, int N, int K, const float* __restrict__ bias,
    const float* __restrict__ shiftCache)
{
    __shared__ uint32_t As[2][BMg * PADg];
    __shared__ uint32_t Bs[2][BNg * PADg];

    const int tid = threadIdx.x;
    const int lane = tid & 31;
    const int warp = tid >> 5;
    const int wm = warp >> 2;
    const int wn = warp & 3;
    const int bm = blockIdx.y * BMg;
    const int bn = blockIdx.x * BNg;
    const int mBase = wm * 64;
    const int nBase = wn * 32;

    // staging chunk coords: chunk0 = tid, chunk1 = tid + 256
    const int r0 = tid >> 2;
    const int cf0 = (tid & 3) << 2;
    const int r1 = r0 + 64;

    // precomputed shifted row pointers for segment-1 A reads (rows bm+r0, bm+r1)
    const float* arow0;
    const float* arow1;
    {
        int m0 = bm + r0, m1 = bm + r1;
        if (shiftCache) {
            arow0 = (m0 % Ss == 0) ? (shiftCache + (size_t)(m0 / Ss) * K)
                                   : (A + (size_t)(m0 - 1) * K);
            arow1 = (m1 % Ss == 0) ? (shiftCache + (size_t)(m1 / Ss) * K)
                                   : (A + (size_t)(m1 - 1) * K);
        } else {
            arow0 = A + (size_t)m0 * K;
            arow1 = A + (size_t)m1 * K;
        }
    }

    float acc[4][4][4];
#pragma unroll
    for (int mi = 0; mi < 4; mi++)
#pragma unroll
        for (int ni = 0; ni < 4; ni++)
#pragma unroll
            for (int e = 0; e < 4; e++) acc[mi][ni][e] = 0.f;

    const int nk = K / BKg;
    const int nkt = A2 ? (2 * nk) : nk;

    // prefetch kt = 0 (segment 1)
    float4 ra0 = *(const float4*)(arow0 + cf0);
    float4 ra1 = *(const float4*)(arow1 + cf0);
    float4 rb0 = *(const float4*)(W + (size_t)(bn + r0) * K + cf0);
    float4 rb1 = *(const float4*)(W + (size_t)(bn + r1) * K + cf0);

    const int row4 = lane >> 2;
    const int col4 = lane & 3;

    for (int kt = 0; kt < nkt; kt++) {
        int buf = kt & 1;
        sts_cvt(&As[buf][r0 * PADg + cf0], ra0);
        sts_cvt(&As[buf][r1 * PADg + cf0], ra1);
        sts_cvt(&Bs[buf][r0 * PADg + cf0], rb0);
        sts_cvt(&Bs[buf][r1 * PADg + cf0], rb1);
        __syncthreads();

        if (kt + 1 < nkt) {
            int k2 = kt + 1;
            if (k2 < nk) {
                int ko = k2 * BKg;
                ra0 = *(const float4*)(arow0 + ko + cf0);
                ra1 = *(const float4*)(arow1 + ko + cf0);
                rb0 = *(const float4*)(W + (size_t)(bn + r0) * K + ko + cf0);
                rb1 = *(const float4*)(W + (size_t)(bn + r1) * K + ko + cf0);
            } else {
                int ko = (k2 - nk) * BKg;
                ra0 = *(const float4*)(A2 + (size_t)(bm + r0) * K + ko + cf0);
                ra1 = *(const float4*)(A2 + (size_t)(bm + r1) * K + ko + cf0);
                rb0 = *(const float4*)(W2 + (size_t)(bn + r0) * K + ko + cf0);
                rb1 = *(const float4*)(W2 + (size_t)(bn + r1) * K + ko + cf0);
            }
        }

        const uint32_t* as = As[buf];
        const uint32_t* bs = Bs[buf];
#pragma unroll
        for (int kk = 0; kk < BKg; kk += 8) {
            uint32_t af[4][4], bf[4][2];
#pragma unroll
            for (int mi = 0; mi < 4; mi++) {
                int m0 = mBase + mi * 16;
                af[mi][0] = as[(m0 + row4) * PADg + kk + col4];
                af[mi][1] = as[(m0 + row4 + 8) * PADg + kk + col4];
                af[mi][2] = as[(m0 + row4) * PADg + kk + col4 + 4];
                af[mi][3] = as[(m0 + row4 + 8) * PADg + kk + col4 + 4];
            }
#pragma unroll
            for (int ni = 0; ni < 4; ni++) {
                int n0 = nBase + ni * 8;
                bf[ni][0] = bs[(n0 + row4) * PADg + kk + col4];
                bf[ni][1] = bs[(n0 + row4) * PADg + kk + col4 + 4];
            }
#pragma unroll
            for (int mi = 0; mi < 4; mi++)
#pragma unroll
                for (int ni = 0; ni < 4; ni++)
                    mma_tf32(acc[mi][ni], af[mi], bf[ni]);
        }
        // one barrier per k-tile: STS(kt+1) targets buf^1, last read in compute(kt-1),
        // fully ordered by the barrier above (validated in R6).
    }

#pragma unroll
    for (int mi = 0; mi < 4; mi++) {
        int r = bm + mBase + mi * 16 + row4;
#pragma unroll
        for (int ni = 0; ni < 4; ni++) {
            int cb = bn + nBase + ni * 8 + 2 * col4;
            float2 b2 = make_float2(0.f, 0.f);
            if (bias) { b2.x = bias[cb]; b2.y = bias[cb + 1]; }
            float2 v0 = make_float2(acc[mi][ni][0] + b2.x, acc[mi][ni][1] + b2.y);
            float2 v1 = make_float2(acc[mi][ni][2] + b2.x, acc[mi][ni][3] + b2.y);
            *(float2*)(C + (size_t)r * N + cb) = v0;
            *(float2*)(C + (size_t)(r + 8) * N + cb) = v1;
        }
    }
}

// ---------------- residual add + RMSNorm ----------------
__global__ __launch_bounds__(256) void rmsnorm_kernel(
    float* __restrict__ y2, const float* __restrict__ x, const float* __restrict__ w)
{
    int m = blockIdx.x;
    float* yrow = y2 + (size_t)m * Hh;
    const float* xrow = x + (size_t)m * Hh;

    float ss = 0.f;
    for (int i = threadIdx.x; i < Hh; i += 256) {
        float t = yrow[i] + xrow[i];
        ss += t * t;
    }
#pragma unroll
    for (int off = 16; off > 0; off >>= 1)
        ss += __shfl_xor_sync(0xffffffffu, ss, off);

    __shared__ float red[9];
    int lane = threadIdx.x & 31, wid = threadIdx.x >> 5;
    if (lane == 0) red[wid] = ss;
    __syncthreads();
    if (threadIdx.x == 0) {
        float tot = 0.f;
        for (int i = 0; i < 8; i++) tot += red[i];
        red[8] = rsqrtf(tot / (float)Hh + EPSc);
    }
    __syncthreads();
    float inv = red[8];
    for (int i = threadIdx.x; i < Hh; i += 256) {
        float t = yrow[i] + xrow[i];
        yrow[i] = t * w[i] * inv;
    }
}

// ---------------- RoPE in place on qk buffer ----------------
__global__ __launch_bounds__(128) void rope_kernel(
    float* __restrict__ qkbuf, const float* __restrict__ freqs,
    const int* __restrict__ positions)
{
    int mh = blockIdx.x;
    int m = mh / NHh, h = mh % NHh;
    int pos = positions[m];
    int t = threadIdx.x;
    int isK = t >> 6;
    int d = t & 63;

    size_t base = (size_t)m * QKW + (size_t)h * 256 + (size_t)isK * 128;
    float f1 = freqs[(size_t)pos * HDd + d];
    float f2 = freqs[(size_t)pos * HDd + d + 64];
    float c1 = cosf(f1), s1 = sinf(f1);
    float c2 = cosf(f2), s2 = sinf(f2);
    float x1 = qkbuf[base + d];
    float x2 = qkbuf[base + d + 64];
    qkbuf[base + d]      = x1 * c1 - x2 * s1;
    qkbuf[base + d + 64] = x2 * c2 + x1 * s2;
}

// ---------------- tensor-core causal flash attention (mma.sync tf32) ----------------
#define FTQ 128
#define FTK 32
#define FPD 132
#define FPP 36
#define FQ_SZ (FTQ * FPD)
#define FK_SZ (FTK * FPD)
#define FP_SZ (FTQ * FPP)
#define FSMEM_BYTES ((2 * FQ_SZ + 3 * FK_SZ + FP_SZ) * 4)

__global__ __launch_bounds__(256, 1) void flash_tc_kernel(
    const float* __restrict__ qkbuf, const float* __restrict__ vbuf,
    float* __restrict__ attn)
{
    extern __shared__ uint32_t fsm[];
    uint32_t* Qhi = fsm;
    uint32_t* Qlo = Qhi + FQ_SZ;
    uint32_t* Khi = Qlo + FQ_SZ;
    uint32_t* Klo = Khi + FK_SZ;
    uint32_t* Vs  = Klo + FK_SZ;
    uint32_t* Ps  = Vs  + FK_SZ;

    const int qt = gridDim.x - 1 - blockIdx.x;
    const int h  = blockIdx.y;
    const int b  = blockIdx.z;
    const int q0 = qt * FTQ;
    const int tid  = threadIdx.x;
    const int lane = tid & 31;
    const int warp = tid >> 5;
    const int wm16 = warp * 16;
    const int row4 = lane >> 2;
    const int col4 = lane & 3;
    const int bS = b * Ss;
    const int hq = h * 256;
    const float scale = 0.08838834764831845f;

    for (int c = tid; c < FTQ * 32; c += 256) {
        int row = c >> 5, colf = (c & 31) << 2;
        float4 q4 = *(const float4*)(qkbuf + (size_t)(bS + q0 + row) * QKW + hq + colf);
        uint4 hi, lo; float x;
        x = q4.x * scale; hi.x = f2tf(x); lo.x = f2tf(x - __uint_as_float(hi.x));
        x = q4.y * scale; hi.y = f2tf(x); lo.y = f2tf(x - __uint_as_float(hi.y));
        x = q4.z * scale; hi.z = f2tf(x); lo.z = f2tf(x - __uint_as_float(hi.z));
        x = q4.w * scale; hi.w = f2tf(x); lo.w = f2tf(x - __uint_as_float(hi.w));
        *(uint4*)&Qhi[row * FPD + colf] = hi;
        *(uint4*)&Qlo[row * FPD + colf] = lo;
    }

    float O[16][4];
#pragma unroll
    for (int ni = 0; ni < 16; ni++)
#pragma unroll
        for (int e = 0; e < 4; e++) O[ni][e] = 0.f;
    float mrow0 = -1e30f, mrow1 = -1e30f, lrow0 = 0.f, lrow1 = 0.f;

    const int kend = q0 + FTQ;
    for (int j0 = 0; j0 < kend; j0 += FTK) {
        __syncthreads();
        for (int c = tid; c < FTK * 32; c += 256) {
            int row = c >> 5, colf = (c & 31) << 2;
            float4 k4 = *(const float4*)(qkbuf + (size_t)(bS + j0 + row) * QKW + hq + 128 + colf);
            uint4 hi, lo;
            hi.x = f2tf(k4.x); lo.x = f2tf(k4.x - __uint_as_float(hi.x));
            hi.y = f2tf(k4.y); lo.y = f2tf(k4.y - __uint_as_float(hi.y));
            hi.z = f2tf(k4.z); lo.z = f2tf(k4.z - __uint_as_float(hi.z));
            hi.w = f2tf(k4.w); lo.w = f2tf(k4.w - __uint_as_float(hi.w));
            *(uint4*)&Khi[row * FPD + colf] = hi;
            *(uint4*)&Klo[row * FPD + colf] = lo;
            float4 v4 = *(const float4*)(vbuf + (size_t)(bS + j0 + row) * Pp + h * HDd + colf);
            uint4 vv;
            vv.x = f2tf(v4.x); vv.y = f2tf(v4.y); vv.z = f2tf(v4.z); vv.w = f2tf(v4.w);
            *(uint4*)&Vs[row * FPD + colf] = vv;
        }
        __syncthreads();

        bool active = (j0 <= q0 + wm16 + 15);
        if (active) {
            float s[4][4];
#pragma unroll
            for (int ni = 0; ni < 4; ni++)
#pragma unroll
                for (int e = 0; e < 4; e++) s[ni][e] = 0.f;

#pragma unroll
            for (int kk = 0; kk < HDd; kk += 8) {
                int ra = (wm16 + row4) * FPD + kk + col4;
                int rb8 = ra + 8 * FPD;
                uint32_t ahi[4] = {Qhi[ra], Qhi[rb8], Qhi[ra + 4], Qhi[rb8 + 4]};
                uint32_t alo[4] = {Qlo[ra], Qlo[rb8], Qlo[ra + 4], Qlo[rb8 + 4]};
#pragma unroll
                for (int ni = 0; ni < 4; ni++) {
                    int rn = (ni * 8 + row4) * FPD + kk + col4;
                    uint32_t bh[2] = {Khi[rn], Khi[rn + 4]};
                    uint32_t bl[2] = {Klo[rn], Klo[rn + 4]};
                    mma_tf32(s[ni], ahi, bh);
                    mma_tf32(s[ni], alo, bh);
                    mma_tf32(s[ni], ahi, bl);
                }
            }

            if (j0 + FTK - 1 > q0 + wm16) {
                int qlo = q0 + wm16 + row4;
                int qhi = qlo + 8;
#pragma unroll
                for (int ni = 0; ni < 4; ni++) {
                    int kp = j0 + ni * 8 + 2 * col4;
                    if (kp     > qlo) s[ni][0] = -1e30f;
                    if (kp + 1 > qlo) s[ni][1] = -1e30f;
                    if (kp     > qhi) s[ni][2] = -1e30f;
                    if (kp + 1 > qhi) s[ni][3] = -1e30f;
                }
            }

            float mx0 = -1e30f, mx1 = -1e30f;
#pragma unroll
            for (int ni = 0; ni < 4; ni++) {
                mx0 = fmaxf(mx0, fmaxf(s[ni][0], s[ni][1]));
                mx1 = fmaxf(mx1, fmaxf(s[ni][2], s[ni][3]));
            }
            mx0 = fmaxf(mx0, __shfl_xor_sync(0xffffffffu, mx0, 1));
            mx0 = fmaxf(mx0, __shfl_xor_sync(0xffffffffu, mx0, 2));
            mx1 = fmaxf(mx1, __shfl_xor_sync(0xffffffffu, mx1, 1));
            mx1 = fmaxf(mx1, __shfl_xor_sync(0xffffffffu, mx1, 2));
            float mn0 = fmaxf(mrow0, mx0), mn1 = fmaxf(mrow1, mx1);
            float al0 = __expf(mrow0 - mn0), al1 = __expf(mrow1 - mn1);
            mrow0 = mn0; mrow1 = mn1;

            float sum0 = 0.f, sum1 = 0.f;
            int pbase = (wm16 + row4) * FPP + 2 * col4;
#pragma unroll
            for (int ni = 0; ni < 4; ni++) {
                float p0 = __expf(s[ni][0] - mn0);
                float p1 = __expf(s[ni][1] - mn0);
                float p2 = __expf(s[ni][2] - mn1);
                float p3 = __expf(s[ni][3] - mn1);
                sum0 += p0 + p1; sum1 += p2 + p3;
                Ps[pbase + ni * 8]               = f2tf(p0);
                Ps[pbase + ni * 8 + 1]           = f2tf(p1);
                Ps[pbase + ni * 8 + 8 * FPP]     = f2tf(p2);
                Ps[pbase + ni * 8 + 8 * FPP + 1] = f2tf(p3);
            }
            lrow0 = lrow0 * al0 + sum0;
            lrow1 = lrow1 * al1 + sum1;
#pragma unroll
            for (int ni = 0; ni < 16; ni++) {
                O[ni][0] *= al0; O[ni][1] *= al0;
                O[ni][2] *= al1; O[ni][3] *= al1;
            }
            __syncwarp();

#pragma unroll
            for (int kp = 0; kp < FTK; kp += 8) {
                int pa = (wm16 + row4) * FPP + kp + col4;
                uint32_t a[4] = {Ps[pa], Ps[pa + 8 * FPP], Ps[pa + 4], Ps[pa + 8 * FPP + 4]};
#pragma unroll
                for (int ni = 0; ni < 16; ni++) {
                    int vb = (kp + col4) * FPD + ni * 8 + row4;
                    uint32_t bv[2] = {Vs[vb], Vs[vb + 4 * FPD]};
                    mma_tf32(O[ni], a, bv);
                }
            }
        }
    }

    lrow0 += __shfl_xor_sync(0xffffffffu, lrow0, 1);
    lrow0 += __shfl_xor_sync(0xffffffffu, lrow0, 2);
    lrow1 += __shfl_xor_sync(0xffffffffu, lrow1, 1);
    lrow1 += __shfl_xor_sync(0xffffffffu, lrow1, 2);
    float inv0 = 1.f / lrow0, inv1 = 1.f / lrow1;

    size_t ob0 = (size_t)(bS + q0 + wm16 + row4) * Pp + h * HDd;
    size_t ob1 = ob0 + (size_t)8 * Pp;
#pragma unroll
    for (int ni = 0; ni < 16; ni++) {
        int cb = ni * 8 + 2 * col4;
        *(float2*)(attn + ob0 + cb) = make_float2(O[ni][0] * inv0, O[ni][1] * inv0);
        *(float2*)(attn + ob1 + cb) = make_float2(O[ni][2] * inv1, O[ni][3] * inv1);
    }
}

// ---------------- tail outputs ----------------
__global__ void tails_kernel(const float* __restrict__ hs, const float* __restrict__ y1,
                             float* __restrict__ out)
{
    int i = blockIdx.x * 256 + threadIdx.x;
    size_t off1 = (size_t)Mm * Hh;
    size_t off2 = off1 + (size_t)Bb * Hh;
    if (i < Bb * Hh) {
        int b = i / Hh, hh = i % Hh;
        out[off1 + i] = hs[((size_t)b * Ss + (Ss - 1)) * Hh + hh];
    }
    if (i < Bb * H2) {
        int b = i / H2, oo = i % H2;
        out[off2 + i] = y1[((size_t)b * Ss + (Ss - 1)) * H2 + oo];
    }
}

// ---------------- launch ----------------
extern "C" void kernel_launch(void* const* d_in, const int* in_sizes, int n_in,
                              void* d_out, int out_size)
{
    (void)in_sizes; (void)n_in; (void)out_size;
    const float* hs      = (const float*)d_in[0];
    const float* freqs   = (const float*)d_in[1];
    const int*   pos     = (const int*)  d_in[2];
    const float* Wqk     = (const float*)d_in[3];
    const float* Wv      = (const float*)d_in[4];
    const float* Wo      = (const float*)d_in[5];
    const float* conv1_w = (const float*)d_in[6];
    const float* conv1_b = (const float*)d_in[7];
    const float* conv2_w = (const float*)d_in[8];
    const float* conv2_b = (const float*)d_in[9];
    const float* ln_w    = (const float*)d_in[10];
    const float* lf1c    = (const float*)d_in[11];
    const float* lf2c    = (const float*)d_in[12];
    float* out = (float*)d_out;

    float *v, *y1, *lfout, *qk, *attn;
    float *w1a, *w1b, *w2a, *w2b;
    cudaGetSymbolAddress((void**)&v,      g_v);
    cudaGetSymbolAddress((void**)&y1,     g_y1);
    cudaGetSymbolAddress((void**)&lfout,  g_lfout);
    cudaGetSymbolAddress((void**)&qk,     g_qk);
    cudaGetSymbolAddress((void**)&attn,   g_attn);
    cudaGetSymbolAddress((void**)&w1a,    g_w1a);
    cudaGetSymbolAddress((void**)&w1b,    g_w1b);
    cudaGetSymbolAddress((void**)&w2a,    g_w2a);
    cudaGetSymbolAddress((void**)&w2b,    g_w2b);

    static bool attr_done = false;
    if (!attr_done) {
        cudaFuncSetAttribute(flash_tc_kernel,
                             cudaFuncAttributeMaxDynamicSharedMemorySize, FSMEM_BYTES);
        attr_done = true;
    }

    // 1) deinterleave conv weights
    {
        int n1 = H2 * Hh;
        deint_kernel<<<(n1 + 255) / 256, 256>>>(conv1_w, w1a, w1b, n1);
        int n2 = Hh * H2;
        deint_kernel<<<(n2 + 255) / 256, 256>>>(conv2_w, w2a, w2b, n2);
    }

    // 2) v = hs @ Wv^T
    gemm_tf32_kernel<<<dim3(Pp / BNg, Mm / BMg), 256>>>(
        hs, Wv, nullptr, nullptr, v, Pp, Hh, nullptr, nullptr);

    // 3) y1 = shift(hs,lf1c) @ w1a^T + hs @ w1b^T + b1  (dual-K, shift fused)
    gemm_tf32_kernel<<<dim3(H2 / BNg, Mm / BMg), 256>>>(
        hs, w1a, hs, w1b, y1, H2, Hh, conv1_b, lf1c);

    // 4) y2 = shift(y1,lf2c) @ w2a^T + y1 @ w2b^T + b2  (dual-K, shift fused)
    gemm_tf32_kernel<<<dim3(Hh / BNg, Mm / BMg), 256>>>(
        y1, w2a, y1, w2b, lfout, Hh, H2, conv2_b, lf2c);

    // 5) lf_out = rmsnorm(y2 + hs) * ln_w
    rmsnorm_kernel<<<Mm, 256>>>(lfout, hs, ln_w);

    // 6) qk = lf_out @ Wqk^T
    gemm_tf32_kernel<<<dim3(QKW / BNg, Mm / BMg), 256>>>(
        lfout, Wqk, nullptr, nullptr, qk, QKW, Hh, nullptr, nullptr);

    // 7) RoPE in place
    rope_kernel<<<Mm * NHh, 128>>>(qk, freqs, pos);

    // 8) tensor-core causal flash attention
    flash_tc_kernel<<<dim3(Ss / FTQ, NHh, Bb), 256, FSMEM_BYTES>>>(qk, v, attn);

    // 9) output = attn @ Wo^T
    gemm_tf32_kernel<<<dim3(Hh / BNg, Mm / BMg), 256>>>(
        attn, Wo, nullptr, nullptr, out, Hh, Pp, nullptr, nullptr);

    // 10) tails
    tails_kernel<<<(Bb * Hh + 255) / 256, 256>>>(hs, y1, out);
}

// round 11
// speedup vs baseline: 1.3001x; 1.1219x over previous
#include <cuda_runtime.h>
#include <cuda_fp16.h>
#include <cuda_bf16.h>
#include <cstdint>
#include <cstddef>

// Problem constants
#define Bb   2
#define Ss   2048
#define Hh   2048
#define NHh  16
#define HDd  128
#define Pp   2048
#define Mm   (Bb * Ss)          // 4096 rows
#define H2   (Hh / 2)           // 1024
#define QKW  (2 * Pp)           // 4096 (qk row width)
#define EPSc 1e-6f

// ---------------- scratch (static device globals; no allocation) ----------------
__device__ float g_v[(size_t)Mm * Pp];
__device__ float g_y1[(size_t)Mm * H2];
__device__ float g_lfout[(size_t)Mm * Hh];
__device__ float g_qk[(size_t)Mm * QKW];
__device__ float g_attn[(size_t)Mm * Pp];
__device__ float g_w1a[(size_t)H2 * Hh];
__device__ float g_w1b[(size_t)H2 * Hh];
__device__ float g_w2a[(size_t)Hh * H2];
__device__ float g_w2b[(size_t)Hh * H2];

// ---------------- helpers ----------------
__device__ __forceinline__ uint32_t f2tf(float x) {
    uint32_t r;
    asm("cvt.rna.tf32.f32 %0, %1;" : "=r"(r) : "f"(x));
    return r;
}

__device__ __forceinline__ void mma_tf32(float* d, const uint32_t* a, const uint32_t* b) {
    asm volatile(
        "mma.sync.aligned.m16n8k8.row.col.f32.tf32.tf32.f32 "
        "{%0,%1,%2,%3},{%4,%5,%6,%7},{%8,%9},{%0,%1,%2,%3};"
        : "+f"(d[0]), "+f"(d[1]), "+f"(d[2]), "+f"(d[3])
        : "r"(a[0]), "r"(a[1]), "r"(a[2]), "r"(a[3]), "r"(b[0]), "r"(b[1]));
}

__device__ __forceinline__ void mma_f16(float* d, const uint32_t* a, const uint32_t* b) {
    asm volatile(
        "mma.sync.aligned.m16n8k16.row.col.f32.f16.f16.f32 "
        "{%0,%1,%2,%3},{%4,%5,%6,%7},{%8,%9},{%0,%1,%2,%3};"
        : "+f"(d[0]), "+f"(d[1]), "+f"(d[2]), "+f"(d[3])
        : "r"(a[0]), "r"(a[1]), "r"(a[2]), "r"(a[3]), "r"(b[0]), "r"(b[1]));
}

__device__ __forceinline__ uint32_t h2pack(float lo, float hi) {
    __half2 h = __floats2half2_rn(lo, hi);
    return *reinterpret_cast<uint32_t*>(&h);
}

struct H16 { uint4 a, b; };   // 16 halves, prefetched & pre-converted

__device__ __forceinline__ H16 ldcvt16(const float* p) {
    float4 f0 = *(const float4*)(p);
    float4 f1 = *(const float4*)(p + 4);
    float4 f2 = *(const float4*)(p + 8);
    float4 f3 = *(const float4*)(p + 12);
    H16 r;
    r.a.x = h2pack(f0.x, f0.y); r.a.y = h2pack(f0.z, f0.w);
    r.a.z = h2pack(f1.x, f1.y); r.a.w = h2pack(f1.z, f1.w);
    r.b.x = h2pack(f2.x, f2.y); r.b.y = h2pack(f2.z, f2.w);
    r.b.z = h2pack(f3.x, f3.y); r.b.w = h2pack(f3.z, f3.w);
    return r;
}

// ---------------- deinterleave conv weights ----------------
__global__ void deint_kernel(const float* __restrict__ in, float* __restrict__ a,
                             float* __restrict__ b, int n)
{
    int i = blockIdx.x * 256 + threadIdx.x;
    if (i < n) {
        a[i] = in[2 * i];
        b[i] = in[2 * i + 1];
    }
}

// ========== FP16 tensor-core GEMM (NT), 128x128 block, warp tile 64x32, BK=32 ==========
// C[M,N] = A1shift[M,K] * W[N,K]^T (+ A2[M,K] * W2[N,K]^T) (+bias)
// If shiftCache != nullptr, segment-1 A-rows are the one-step-shifted view of A:
//   row m reads A[m-1] (or shiftCache[m/Ss] when m%Ss==0).  Segment 2 unshifted.
// fp16 mantissa == tf32 mantissa (11 bits); fp32 accumulate in MMA.
// 8 warps (2x4), m16n8k16.  M%128==0, N%128==0, K%32==0.
#define BMh 128
#define BNh 128
#define BKh 32
#define PWH 20    // row pitch in 4B words (= 40 halves); data occupies words [0,16)

__global__ __launch_bounds__(256, 2) void gemm_fp16_kernel(
    const float* __restrict__ A, const float* __restrict__ W,
    const float* __restrict__ A2, const float* __restrict__ W2,
    float* __restrict__ C, int N, int K, const float* __restrict__ bias,
    const float* __restrict__ shiftCache)
{
    __shared__ uint32_t As[2][BMh * PWH];   // 2 x 10 KB
    __shared__ uint32_t Bs[2][BNh * PWH];   // 2 x 10 KB   (40 KB total)

    const int tid = threadIdx.x;
    const int lane = tid & 31;
    const int warp = tid >> 5;
    const int wm = warp >> 2;            // 0..1  (64 rows)
    const int wn = warp & 3;             // 0..3  (32 cols)
    const int bm = blockIdx.y * BMh;
    const int bn = blockIdx.x * BNh;
    const int mBase = wm * 64;
    const int nBase = wn * 32;

    // staging coords: thread t -> row ra = t>>1, k-segment seg = t&1 (16 halves)
    const int ra = tid >> 1;
    const int seg = tid & 1;
    const int sk = seg * 16;             // k offset in elements
    const int sw = seg * 8;              // word offset in smem row

    // shift-aware segment-1 A row pointer for row bm+ra
    const float* arow;
    {
        int m = bm + ra;
        if (shiftCache) {
            arow = (m % Ss == 0) ? (shiftCache + (size_t)(m / Ss) * K)
                                 : (A + (size_t)(m - 1) * K);
        } else {
            arow = A + (size_t)m * K;
        }
    }
    const float* wrow = W + (size_t)(bn + ra) * K;
    const float* a2row = A2 ? (A2 + (size_t)(bm + ra) * K) : nullptr;
    const float* w2row = W2 ? (W2 + (size_t)(bn + ra) * K) : nullptr;

    float acc[4][4][4];
#pragma unroll
    for (int mi = 0; mi < 4; mi++)
#pragma unroll
        for (int ni = 0; ni < 4; ni++)
#pragma unroll
            for (int e = 0; e < 4; e++) acc[mi][ni][e] = 0.f;

    const int nk = K / BKh;
    const int nkt = A2 ? (2 * nk) : nk;

    // prefetch kt = 0 (convert to half at load time: 16 regs per matrix -> 8)
    H16 pa = ldcvt16(arow + sk);
    H16 pb = ldcvt16(wrow + sk);

    const int row4 = lane >> 2;
    const int col4 = lane & 3;

    for (int kt = 0; kt < nkt; kt++) {
        int buf = kt & 1;
        {
            uint32_t* ap = &As[buf][ra * PWH + sw];
            uint32_t* bp = &Bs[buf][ra * PWH + sw];
            *(uint4*)(ap) = pa.a;  *(uint4*)(ap + 4) = pa.b;
            *(uint4*)(bp) = pb.a;  *(uint4*)(bp + 4) = pb.b;
        }
        __syncthreads();

        if (kt + 1 < nkt) {
            int k2 = kt + 1;
            if (k2 < nk) {
                int ko = k2 * BKh + sk;
                pa = ldcvt16(arow + ko);
                pb = ldcvt16(wrow + ko);
            } else {
                int ko = (k2 - nk) * BKh + sk;
                pa = ldcvt16(a2row + ko);
                pb = ldcvt16(w2row + ko);
            }
        }

        const uint32_t* as = As[buf];
        const uint32_t* bs = Bs[buf];
#pragma unroll
        for (int kw = 0; kw < 16; kw += 8) {     // two k16 steps (word offsets)
            uint32_t af[4][4], bf[4][2];
#pragma unroll
            for (int mi = 0; mi < 4; mi++) {
                int m0 = mBase + mi * 16;
                af[mi][0] = as[(m0 + row4) * PWH + kw + col4];
                af[mi][1] = as[(m0 + row4 + 8) * PWH + kw + col4];
                af[mi][2] = as[(m0 + row4) * PWH + kw + col4 + 4];
                af[mi][3] = as[(m0 + row4 + 8) * PWH + kw + col4 + 4];
            }
#pragma unroll
            for (int ni = 0; ni < 4; ni++) {
                int n0 = nBase + ni * 8;
                bf[ni][0] = bs[(n0 + row4) * PWH + kw + col4];
                bf[ni][1] = bs[(n0 + row4) * PWH + kw + col4 + 4];
            }
#pragma unroll
            for (int mi = 0; mi < 4; mi++)
#pragma unroll
                for (int ni = 0; ni < 4; ni++)
                    mma_f16(acc[mi][ni], af[mi], bf[ni]);
        }
        // one barrier per kt: STS(kt+1) targets buf^1, last read in compute(kt-1),
        // fully ordered by the barrier above (same scheme as validated R6 kernel).
    }

#pragma unroll
    for (int mi = 0; mi < 4; mi++) {
        int r = bm + mBase + mi * 16 + row4;
#pragma unroll
        for (int ni = 0; ni < 4; ni++) {
            int cb = bn + nBase + ni * 8 + 2 * col4;
            float2 b2 = make_float2(0.f, 0.f);
            if (bias) { b2.x = bias[cb]; b2.y = bias[cb + 1]; }
            float2 v0 = make_float2(acc[mi][ni][0] + b2.x, acc[mi][ni][1] + b2.y);
            float2 v1 = make_float2(acc[mi][ni][2] + b2.x, acc[mi][ni][3] + b2.y);
            *(float2*)(C + (size_t)r * N + cb) = v0;
            *(float2*)(C + (size_t)(r + 8) * N + cb) = v1;
        }
    }
}

// ---------------- residual add + RMSNorm ----------------
__global__ __launch_bounds__(256) void rmsnorm_kernel(
    float* __restrict__ y2, const float* __restrict__ x, const float* __restrict__ w)
{
    int m = blockIdx.x;
    float* yrow = y2 + (size_t)m * Hh;
    const float* xrow = x + (size_t)m * Hh;

    float ss = 0.f;
    for (int i = threadIdx.x; i < Hh; i += 256) {
        float t = yrow[i] + xrow[i];
        ss += t * t;
    }
#pragma unroll
    for (int off = 16; off > 0; off >>= 1)
        ss += __shfl_xor_sync(0xffffffffu, ss, off);

    __shared__ float red[9];
    int lane = threadIdx.x & 31, wid = threadIdx.x >> 5;
    if (lane == 0) red[wid] = ss;
    __syncthreads();
    if (threadIdx.x == 0) {
        float tot = 0.f;
        for (int i = 0; i < 8; i++) tot += red[i];
        red[8] = rsqrtf(tot / (float)Hh + EPSc);
    }
    __syncthreads();
    float inv = red[8];
    for (int i = threadIdx.x; i < Hh; i += 256) {
        float t = yrow[i] + xrow[i];
        yrow[i] = t * w[i] * inv;
    }
}

// ---------------- RoPE in place on qk buffer ----------------
__global__ __launch_bounds__(128) void rope_kernel(
    float* __restrict__ qkbuf, const float* __restrict__ freqs,
    const int* __restrict__ positions)
{
    int mh = blockIdx.x;
    int m = mh / NHh, h = mh % NHh;
    int pos = positions[m];
    int t = threadIdx.x;
    int isK = t >> 6;
    int d = t & 63;

    size_t base = (size_t)m * QKW + (size_t)h * 256 + (size_t)isK * 128;
    float f1 = freqs[(size_t)pos * HDd + d];
    float f2 = freqs[(size_t)pos * HDd + d + 64];
    float c1 = cosf(f1), s1 = sinf(f1);
    float c2 = cosf(f2), s2 = sinf(f2);
    float x1 = qkbuf[base + d];
    float x2 = qkbuf[base + d + 64];
    qkbuf[base + d]      = x1 * c1 - x2 * s1;
    qkbuf[base + d + 64] = x2 * c2 + x1 * s2;
}

// ---------------- tensor-core causal flash attention (mma.sync tf32) ----------------
#define FTQ 128
#define FTK 32
#define FPD 132
#define FPP 36
#define FQ_SZ (FTQ * FPD)
#define FK_SZ (FTK * FPD)
#define FP_SZ (FTQ * FPP)
#define FSMEM_BYTES ((2 * FQ_SZ + 3 * FK_SZ + FP_SZ) * 4)

__global__ __launch_bounds__(256, 1) void flash_tc_kernel(
    const float* __restrict__ qkbuf, const float* __restrict__ vbuf,
    float* __restrict__ attn)
{
    extern __shared__ uint32_t fsm[];
    uint32_t* Qhi = fsm;
    uint32_t* Qlo = Qhi + FQ_SZ;
    uint32_t* Khi = Qlo + FQ_SZ;
    uint32_t* Klo = Khi + FK_SZ;
    uint32_t* Vs  = Klo + FK_SZ;
    uint32_t* Ps  = Vs  + FK_SZ;

    const int qt = gridDim.x - 1 - blockIdx.x;
    const int h  = blockIdx.y;
    const int b  = blockIdx.z;
    const int q0 = qt * FTQ;
    const int tid  = threadIdx.x;
    const int lane = tid & 31;
    const int warp = tid >> 5;
    const int wm16 = warp * 16;
    const int row4 = lane >> 2;
    const int col4 = lane & 3;
    const int bS = b * Ss;
    const int hq = h * 256;
    const float scale = 0.08838834764831845f;

    for (int c = tid; c < FTQ * 32; c += 256) {
        int row = c >> 5, colf = (c & 31) << 2;
        float4 q4 = *(const float4*)(qkbuf + (size_t)(bS + q0 + row) * QKW + hq + colf);
        uint4 hi, lo; float x;
        x = q4.x * scale; hi.x = f2tf(x); lo.x = f2tf(x - __uint_as_float(hi.x));
        x = q4.y * scale; hi.y = f2tf(x); lo.y = f2tf(x - __uint_as_float(hi.y));
        x = q4.z * scale; hi.z = f2tf(x); lo.z = f2tf(x - __uint_as_float(hi.z));
        x = q4.w * scale; hi.w = f2tf(x); lo.w = f2tf(x - __uint_as_float(hi.w));
        *(uint4*)&Qhi[row * FPD + colf] = hi;
        *(uint4*)&Qlo[row * FPD + colf] = lo;
    }

    float O[16][4];
#pragma unroll
    for (int ni = 0; ni < 16; ni++)
#pragma unroll
        for (int e = 0; e < 4; e++) O[ni][e] = 0.f;
    float mrow0 = -1e30f, mrow1 = -1e30f, lrow0 = 0.f, lrow1 = 0.f;

    const int kend = q0 + FTQ;
    for (int j0 = 0; j0 < kend; j0 += FTK) {
        __syncthreads();
        for (int c = tid; c < FTK * 32; c += 256) {
            int row = c >> 5, colf = (c & 31) << 2;
            float4 k4 = *(const float4*)(qkbuf + (size_t)(bS + j0 + row) * QKW + hq + 128 + colf);
            uint4 hi, lo;
            hi.x = f2tf(k4.x); lo.x = f2tf(k4.x - __uint_as_float(hi.x));
            hi.y = f2tf(k4.y); lo.y = f2tf(k4.y - __uint_as_float(hi.y));
            hi.z = f2tf(k4.z); lo.z = f2tf(k4.z - __uint_as_float(hi.z));
            hi.w = f2tf(k4.w); lo.w = f2tf(k4.w - __uint_as_float(hi.w));
            *(uint4*)&Khi[row * FPD + colf] = hi;
            *(uint4*)&Klo[row * FPD + colf] = lo;
            float4 v4 = *(const float4*)(vbuf + (size_t)(bS + j0 + row) * Pp + h * HDd + colf);
            uint4 vv;
            vv.x = f2tf(v4.x); vv.y = f2tf(v4.y); vv.z = f2tf(v4.z); vv.w = f2tf(v4.w);
            *(uint4*)&Vs[row * FPD + colf] = vv;
        }
        __syncthreads();

        bool active = (j0 <= q0 + wm16 + 15);
        if (active) {
            float s[4][4];
#pragma unroll
            for (int ni = 0; ni < 4; ni++)
#pragma unroll
                for (int e = 0; e < 4; e++) s[ni][e] = 0.f;

#pragma unroll
            for (int kk = 0; kk < HDd; kk += 8) {
                int ra = (wm16 + row4) * FPD + kk + col4;
                int rb8 = ra + 8 * FPD;
                uint32_t ahi[4] = {Qhi[ra], Qhi[rb8], Qhi[ra + 4], Qhi[rb8 + 4]};
                uint32_t alo[4] = {Qlo[ra], Qlo[rb8], Qlo[ra + 4], Qlo[rb8 + 4]};
#pragma unroll
                for (int ni = 0; ni < 4; ni++) {
                    int rn = (ni * 8 + row4) * FPD + kk + col4;
                    uint32_t bh[2] = {Khi[rn], Khi[rn + 4]};
                    uint32_t bl[2] = {Klo[rn], Klo[rn + 4]};
                    mma_tf32(s[ni], ahi, bh);
                    mma_tf32(s[ni], alo, bh);
                    mma_tf32(s[ni], ahi, bl);
                }
            }

            if (j0 + FTK - 1 > q0 + wm16) {
                int qlo = q0 + wm16 + row4;
                int qhi = qlo + 8;
#pragma unroll
                for (int ni = 0; ni < 4; ni++) {
                    int kp = j0 + ni * 8 + 2 * col4;
                    if (kp     > qlo) s[ni][0] = -1e30f;
                    if (kp + 1 > qlo) s[ni][1] = -1e30f;
                    if (kp     > qhi) s[ni][2] = -1e30f;
                    if (kp + 1 > qhi) s[ni][3] = -1e30f;
                }
            }

            float mx0 = -1e30f, mx1 = -1e30f;
#pragma unroll
            for (int ni = 0; ni < 4; ni++) {
                mx0 = fmaxf(mx0, fmaxf(s[ni][0], s[ni][1]));
                mx1 = fmaxf(mx1, fmaxf(s[ni][2], s[ni][3]));
            }
            mx0 = fmaxf(mx0, __shfl_xor_sync(0xffffffffu, mx0, 1));
            mx0 = fmaxf(mx0, __shfl_xor_sync(0xffffffffu, mx0, 2));
            mx1 = fmaxf(mx1, __shfl_xor_sync(0xffffffffu, mx1, 1));
            mx1 = fmaxf(mx1, __shfl_xor_sync(0xffffffffu, mx1, 2));
            float mn0 = fmaxf(mrow0, mx0), mn1 = fmaxf(mrow1, mx1);
            float al0 = __expf(mrow0 - mn0), al1 = __expf(mrow1 - mn1);
            mrow0 = mn0; mrow1 = mn1;

            float sum0 = 0.f, sum1 = 0.f;
            int pbase = (wm16 + row4) * FPP + 2 * col4;
#pragma unroll
            for (int ni = 0; ni < 4; ni++) {
                float p0 = __expf(s[ni][0] - mn0);
                float p1 = __expf(s[ni][1] - mn0);
                float p2 = __expf(s[ni][2] - mn1);
                float p3 = __expf(s[ni][3] - mn1);
                sum0 += p0 + p1; sum1 += p2 + p3;
                Ps[pbase + ni * 8]               = f2tf(p0);
                Ps[pbase + ni * 8 + 1]           = f2tf(p1);
                Ps[pbase + ni * 8 + 8 * FPP]     = f2tf(p2);
                Ps[pbase + ni * 8 + 8 * FPP + 1] = f2tf(p3);
            }
            lrow0 = lrow0 * al0 + sum0;
            lrow1 = lrow1 * al1 + sum1;
#pragma unroll
            for (int ni = 0; ni < 16; ni++) {
                O[ni][0] *= al0; O[ni][1] *= al0;
                O[ni][2] *= al1; O[ni][3] *= al1;
            }
            __syncwarp();

#pragma unroll
            for (int kp = 0; kp < FTK; kp += 8) {
                int pa = (wm16 + row4) * FPP + kp + col4;
                uint32_t a[4] = {Ps[pa], Ps[pa + 8 * FPP], Ps[pa + 4], Ps[pa + 8 * FPP + 4]};
#pragma unroll
                for (int ni = 0; ni < 16; ni++) {
                    int vb = (kp + col4) * FPD + ni * 8 + row4;
                    uint32_t bv[2] = {Vs[vb], Vs[vb + 4 * FPD]};
                    mma_tf32(O[ni], a, bv);
                }
            }
        }
    }

    lrow0 += __shfl_xor_sync(0xffffffffu, lrow0, 1);
    lrow0 += __shfl_xor_sync(0xffffffffu, lrow0, 2);
    lrow1 += __shfl_xor_sync(0xffffffffu, lrow1, 1);
    lrow1 += __shfl_xor_sync(0xffffffffu, lrow1, 2);
    float inv0 = 1.f / lrow0, inv1 = 1.f / lrow1;

    size_t ob0 = (size_t)(bS + q0 + wm16 + row4) * Pp + h * HDd;
    size_t ob1 = ob0 + (size_t)8 * Pp;
#pragma unroll
    for (int ni = 0; ni < 16; ni++) {
        int cb = ni * 8 + 2 * col4;
        *(float2*)(attn + ob0 + cb) = make_float2(O[ni][0] * inv0, O[ni][1] * inv0);
        *(float2*)(attn + ob1 + cb) = make_float2(O[ni][2] * inv1, O[ni][3] * inv1);
    }
}

// ---------------- tail outputs ----------------
__global__ void tails_kernel(const float* __restrict__ hs, const float* __restrict__ y1,
                             float* __restrict__ out)
{
    int i = blockIdx.x * 256 + threadIdx.x;
    size_t off1 = (size_t)Mm * Hh;
    size_t off2 = off1 + (size_t)Bb * Hh;
    if (i < Bb * Hh) {
        int b = i / Hh, hh = i % Hh;
        out[off1 + i] = hs[((size_t)b * Ss + (Ss - 1)) * Hh + hh];
    }
    if (i < Bb * H2) {
        int b = i / H2, oo = i % H2;
        out[off2 + i] = y1[((size_t)b * Ss + (Ss - 1)) * H2 + oo];
    }
}

// ---------------- launch ----------------
extern "C" void kernel_launch(void* const* d_in, const int* in_sizes, int n_in,
                              void* d_out, int out_size)
{
    (void)in_sizes; (void)n_in; (void)out_size;
    const float* hs      = (const float*)d_in[0];
    const float* freqs   = (const float*)d_in[1];
    const int*   pos     = (const int*)  d_in[2];
    const float* Wqk     = (const float*)d_in[3];
    const float* Wv      = (const float*)d_in[4];
    const float* Wo      = (const float*)d_in[5];
    const float* conv1_w = (const float*)d_in[6];
    const float* conv1_b = (const float*)d_in[7];
    const float* conv2_w = (const float*)d_in[8];
    const float* conv2_b = (const float*)d_in[9];
    const float* ln_w    = (const float*)d_in[10];
    const float* lf1c    = (const float*)d_in[11];
    const float* lf2c    = (const float*)d_in[12];
    float* out = (float*)d_out;

    float *v, *y1, *lfout, *qk, *attn;
    float *w1a, *w1b, *w2a, *w2b;
    cudaGetSymbolAddress((void**)&v,      g_v);
    cudaGetSymbolAddress((void**)&y1,     g_y1);
    cudaGetSymbolAddress((void**)&lfout,  g_lfout);
    cudaGetSymbolAddress((void**)&qk,     g_qk);
    cudaGetSymbolAddress((void**)&attn,   g_attn);
    cudaGetSymbolAddress((void**)&w1a,    g_w1a);
    cudaGetSymbolAddress((void**)&w1b,    g_w1b);
    cudaGetSymbolAddress((void**)&w2a,    g_w2a);
    cudaGetSymbolAddress((void**)&w2b,    g_w2b);

    static bool attr_done = false;
    if (!attr_done) {
        cudaFuncSetAttribute(flash_tc_kernel,
                             cudaFuncAttributeMaxDynamicSharedMemorySize, FSMEM_BYTES);
        attr_done = true;
    }

    // 1) deinterleave conv weights
    {
        int n1 = H2 * Hh;
        deint_kernel<<<(n1 + 255) / 256, 256>>>(conv1_w, w1a, w1b, n1);
        int n2 = Hh * H2;
        deint_kernel<<<(n2 + 255) / 256, 256>>>(conv2_w, w2a, w2b, n2);
    }

    // 2) v = hs @ Wv^T
    gemm_fp16_kernel<<<dim3(Pp / BNh, Mm / BMh), 256>>>(
        hs, Wv, nullptr, nullptr, v, Pp, Hh, nullptr, nullptr);

    // 3) y1 = shift(hs,lf1c) @ w1a^T + hs @ w1b^T + b1  (dual-K, shift fused)
    gemm_fp16_kernel<<<dim3(H2 / BNh, Mm / BMh), 256>>>(
        hs, w1a, hs, w1b, y1, H2, Hh, conv1_b, lf1c);

    // 4) y2 = shift(y1,lf2c) @ w2a^T + y1 @ w2b^T + b2  (dual-K, shift fused)
    gemm_fp16_kernel<<<dim3(Hh / BNh, Mm / BMh), 256>>>(
        y1, w2a, y1, w2b, lfout, Hh, H2, conv2_b, lf2c);

    // 5) lf_out = rmsnorm(y2 + hs) * ln_w
    rmsnorm_kernel<<<Mm, 256>>>(lfout, hs, ln_w);

    // 6) qk = lf_out @ Wqk^T
    gemm_fp16_kernel<<<dim3(QKW / BNh, Mm / BMh), 256>>>(
        lfout, Wqk, nullptr, nullptr, qk, QKW, Hh, nullptr, nullptr);

    // 7) RoPE in place
    rope_kernel<<<Mm * NHh, 128>>>(qk, freqs, pos);

    // 8) tensor-core causal flash attention
    flash_tc_kernel<<<dim3(Ss / FTQ, NHh, Bb), 256, FSMEM_BYTES>>>(qk, v, attn);

    // 9) output = attn @ Wo^T
    gemm_fp16_kernel<<<dim3(Hh / BNh, Mm / BMh), 256>>>(
        attn, Wo, nullptr, nullptr, out, Hh, Pp, nullptr, nullptr);

    // 10) tails
    tails_kernel<<<(Bb * Hh + 255) / 256, 256>>>(hs, y1, out);
}

// round 12
// speedup vs baseline: 1.5794x; 1.2149x over previous
#include <cuda_runtime.h>
#include <cuda_fp16.h>
#include <cuda_bf16.h>
#include <cstdint>
#include <cstddef>

// Problem constants
#define Bb   2
#define Ss   2048
#define Hh   2048
#define NHh  16
#define HDd  128
#define Pp   2048
#define Mm   (Bb * Ss)          // 4096 rows
#define H2   (Hh / 2)           // 1024
#define QKW  (2 * Pp)           // 4096 (qk row width)
#define EPSc 1e-6f

// ---------------- scratch (static device globals; no allocation) ----------------
// fp32
__device__ float g_v[(size_t)Mm * Pp];
__device__ float g_y1[(size_t)Mm * H2];
__device__ float g_lfout[(size_t)Mm * Hh];     // y2 (pre-rmsnorm)
__device__ float g_qk[(size_t)Mm * QKW];
// fp16 operands
__device__ __half g_hs16[(size_t)Mm * Hh];
__device__ __half g_wv16[(size_t)Pp * Hh];
__device__ __half g_wqk16[(size_t)QKW * Hh];
__device__ __half g_wo16[(size_t)Hh * Pp];
__device__ __half g_w1a16[(size_t)H2 * Hh];
__device__ __half g_w1b16[(size_t)H2 * Hh];
__device__ __half g_w2a16[(size_t)Hh * H2];
__device__ __half g_w2b16[(size_t)Hh * H2];
__device__ __half g_y1h[(size_t)Mm * H2];
__device__ __half g_lf16[(size_t)Mm * Hh];
__device__ __half g_attn16[(size_t)Mm * Pp];
__device__ __half g_lf1c16[(size_t)Bb * Hh];
__device__ __half g_lf2c16[(size_t)Bb * H2];

// ---------------- helpers ----------------
__device__ __forceinline__ uint32_t f2tf(float x) {
    uint32_t r;
    asm("cvt.rna.tf32.f32 %0, %1;" : "=r"(r) : "f"(x));
    return r;
}

__device__ __forceinline__ void mma_tf32(float* d, const uint32_t* a, const uint32_t* b) {
    asm volatile(
        "mma.sync.aligned.m16n8k8.row.col.f32.tf32.tf32.f32 "
        "{%0,%1,%2,%3},{%4,%5,%6,%7},{%8,%9},{%0,%1,%2,%3};"
        : "+f"(d[0]), "+f"(d[1]), "+f"(d[2]), "+f"(d[3])
        : "r"(a[0]), "r"(a[1]), "r"(a[2]), "r"(a[3]), "r"(b[0]), "r"(b[1]));
}

__device__ __forceinline__ void mma_f16(float* d, const uint32_t* a, const uint32_t* b) {
    asm volatile(
        "mma.sync.aligned.m16n8k16.row.col.f32.f16.f16.f32 "
        "{%0,%1,%2,%3},{%4,%5,%6,%7},{%8,%9},{%0,%1,%2,%3};"
        : "+f"(d[0]), "+f"(d[1]), "+f"(d[2]), "+f"(d[3])
        : "r"(a[0]), "r"(a[1]), "r"(a[2]), "r"(a[3]), "r"(b[0]), "r"(b[1]));
}

__device__ __forceinline__ uint32_t h2pack(float lo, float hi) {
    __half2 h = __floats2half2_rn(lo, hi);
    return *reinterpret_cast<uint32_t*>(&h);
}

__device__ __forceinline__ void cp16(uint32_t* smem, const void* g) {
    uint32_t s = (uint32_t)__cvta_generic_to_shared(smem);
    asm volatile("cp.async.ca.shared.global [%0], [%1], 16;" :: "r"(s), "l"(g));
}

// ---------------- fp32 -> fp16 conversion (8 elts/thread) ----------------
__global__ void cvt16_kernel(const float* __restrict__ in, __half* __restrict__ out, int n)
{
    int i = (blockIdx.x * 256 + threadIdx.x) * 8;
    if (i < n) {
        float4 f0 = *(const float4*)(in + i);
        float4 f1 = *(const float4*)(in + i + 4);
        uint4 u;
        u.x = h2pack(f0.x, f0.y); u.y = h2pack(f0.z, f0.w);
        u.z = h2pack(f1.x, f1.y); u.w = h2pack(f1.z, f1.w);
        *(uint4*)(out + i) = u;
    }
}

// ---------------- deinterleave conv weights -> fp16 ----------------
__global__ void deint16_kernel(const float* __restrict__ in, __half* __restrict__ a,
                               __half* __restrict__ b, int n)
{
    int i = blockIdx.x * 256 + threadIdx.x;
    if (i < n) {
        a[i] = __float2half_rn(in[2 * i]);
        b[i] = __float2half_rn(in[2 * i + 1]);
    }
}

// ========== FP16 tensor-core GEMM (NT), cp.async 4-stage pipeline ==========
// C[M,N] = A1shift[M,K] * W[N,K]^T (+ A2[M,K] * W2[N,K]^T) (+bias), all operands fp16.
// Optional fp16 mirror C16. Shift fusion as in R10/R11.
// 128x128 block, BK=32 halves, 8 warps (2x4), warp tile 64x32, m16n8k16.
#define BMh 128
#define BNh 128
#define BKh 32
#define PWH 20      // row pitch in 4B words; data words [0,16)
#define NSTG 4
#define STG_W (BMh * PWH)                      // 2560 words per tile-stage
#define GH_SMEM (NSTG * STG_W * 2 * 4)         // 81920 bytes

__global__ __launch_bounds__(256, 2) void gemm_h16_kernel(
    const __half* __restrict__ A, const __half* __restrict__ W,
    const __half* __restrict__ A2, const __half* __restrict__ W2,
    float* __restrict__ C, __half* __restrict__ C16,
    int N, int K, const float* __restrict__ bias,
    const __half* __restrict__ shiftCache)
{
    extern __shared__ uint32_t sh[];
    uint32_t* Abase = sh;                      // NSTG stages of A
    uint32_t* Bbase = sh + NSTG * STG_W;       // NSTG stages of B

    const int tid = threadIdx.x;
    const int lane = tid & 31;
    const int warp = tid >> 5;
    const int wm = warp >> 2;            // 0..1  (64 rows)
    const int wn = warp & 3;             // 0..3  (32 cols)
    const int bm = blockIdx.y * BMh;
    const int bn = blockIdx.x * BNh;
    const int mBase = wm * 64;
    const int nBase = wn * 32;

    // staging coords: thread -> row ra, k-segment seg (16 halves = 32B = 2 chunks)
    const int ra = tid >> 1;
    const int seg = tid & 1;
    const int sk = seg * 16;             // halves
    const int sw = seg * 8;              // words

    // shift-aware segment-1 A row pointer
    const __half* arow;
    {
        int m = bm + ra;
        if (shiftCache) {
            arow = (m % Ss == 0) ? (shiftCache + (size_t)(m / Ss) * K)
                                 : (A + (size_t)(m - 1) * K);
        } else {
            arow = A + (size_t)m * K;
        }
    }
    const __half* wrow  = W + (size_t)(bn + ra) * K;
    const __half* a2row = A2 ? (A2 + (size_t)(bm + ra) * K) : nullptr;
    const __half* w2row = W2 ? (W2 + (size_t)(bn + ra) * K) : nullptr;

    float acc[4][4][4];
#pragma unroll
    for (int mi = 0; mi < 4; mi++)
#pragma unroll
        for (int ni = 0; ni < 4; ni++)
#pragma unroll
            for (int e = 0; e < 4; e++) acc[mi][ni][e] = 0.f;

    const int nk = K / BKh;
    const int nkt = A2 ? (2 * nk) : nk;

    // issue cp.async loads for k-tile kt into stage kt%NSTG
    auto issue = [&](int kt) {
        const __half* ap;
        const __half* wp;
        if (kt < nk) { ap = arow  + kt * BKh + sk;        wp = wrow  + kt * BKh + sk; }
        else         { ap = a2row + (kt - nk) * BKh + sk; wp = w2row + (kt - nk) * BKh + sk; }
        uint32_t* as = Abase + (kt % NSTG) * STG_W + ra * PWH + sw;
        uint32_t* bs = Bbase + (kt % NSTG) * STG_W + ra * PWH + sw;
        cp16(as,     ap);
        cp16(as + 4, ap + 8);
        cp16(bs,     wp);
        cp16(bs + 4, wp + 8);
    };

    // prologue: stages 0..NSTG-2
#pragma unroll
    for (int s = 0; s < NSTG - 1; s++) {
        if (s < nkt) issue(s);
        asm volatile("cp.async.commit_group;");
    }

    const int row4 = lane >> 2;
    const int col4 = lane & 3;

    for (int kt = 0; kt < nkt; kt++) {
        asm volatile("cp.async.wait_group %0;" :: "n"(NSTG - 2));
        __syncthreads();

        // issue next stage (writes slot (kt-1)%NSTG, consumed in compute(kt-1),
        // ordered by the barrier above)
        if (kt + NSTG - 1 < nkt) issue(kt + NSTG - 1);
        asm volatile("cp.async.commit_group;");

        const uint32_t* as = Abase + (kt % NSTG) * STG_W;
        const uint32_t* bs = Bbase + (kt % NSTG) * STG_W;
#pragma unroll
        for (int kw = 0; kw < 16; kw += 8) {   // two k16 steps
            uint32_t af[4][4], bf[4][2];
#pragma unroll
            for (int mi = 0; mi < 4; mi++) {
                int m0 = mBase + mi * 16;
                af[mi][0] = as[(m0 + row4) * PWH + kw + col4];
                af[mi][1] = as[(m0 + row4 + 8) * PWH + kw + col4];
                af[mi][2] = as[(m0 + row4) * PWH + kw + col4 + 4];
                af[mi][3] = as[(m0 + row4 + 8) * PWH + kw + col4 + 4];
            }
#pragma unroll
            for (int ni = 0; ni < 4; ni++) {
                int n0 = nBase + ni * 8;
                bf[ni][0] = bs[(n0 + row4) * PWH + kw + col4];
                bf[ni][1] = bs[(n0 + row4) * PWH + kw + col4 + 4];
            }
#pragma unroll
            for (int mi = 0; mi < 4; mi++)
#pragma unroll
                for (int ni = 0; ni < 4; ni++)
                    mma_f16(acc[mi][ni], af[mi], bf[ni]);
        }
        // barrier at top of next iteration orders reuse of this stage's slot
    }

#pragma unroll
    for (int mi = 0; mi < 4; mi++) {
        int r = bm + mBase + mi * 16 + row4;
#pragma unroll
        for (int ni = 0; ni < 4; ni++) {
            int cb = bn + nBase + ni * 8 + 2 * col4;
            float2 b2 = make_float2(0.f, 0.f);
            if (bias) { b2.x = bias[cb]; b2.y = bias[cb + 1]; }
            float2 v0 = make_float2(acc[mi][ni][0] + b2.x, acc[mi][ni][1] + b2.y);
            float2 v1 = make_float2(acc[mi][ni][2] + b2.x, acc[mi][ni][3] + b2.y);
            *(float2*)(C + (size_t)r * N + cb) = v0;
            *(float2*)(C + (size_t)(r + 8) * N + cb) = v1;
            if (C16) {
                *(uint32_t*)(C16 + (size_t)r * N + cb) = h2pack(v0.x, v0.y);
                *(uint32_t*)(C16 + (size_t)(r + 8) * N + cb) = h2pack(v1.x, v1.y);
            }
        }
    }
}

// ---------------- residual add + RMSNorm -> fp16 output ----------------
__global__ __launch_bounds__(256) void rmsnorm_kernel(
    const float* __restrict__ y2, const float* __restrict__ x,
    const float* __restrict__ w, __half* __restrict__ out16)
{
    int m = blockIdx.x;
    const float* yrow = y2 + (size_t)m * Hh;
    const float* xrow = x + (size_t)m * Hh;

    float ss = 0.f;
    for (int i = threadIdx.x; i < Hh; i += 256) {
        float t = yrow[i] + xrow[i];
        ss += t * t;
    }
#pragma unroll
    for (int off = 16; off > 0; off >>= 1)
        ss += __shfl_xor_sync(0xffffffffu, ss, off);

    __shared__ float red[9];
    int lane = threadIdx.x & 31, wid = threadIdx.x >> 5;
    if (lane == 0) red[wid] = ss;
    __syncthreads();
    if (threadIdx.x == 0) {
        float tot = 0.f;
        for (int i = 0; i < 8; i++) tot += red[i];
        red[8] = rsqrtf(tot / (float)Hh + EPSc);
    }
    __syncthreads();
    float inv = red[8];
    __half* orow = out16 + (size_t)m * Hh;
    for (int i = threadIdx.x; i < Hh; i += 256) {
        float t = (yrow[i] + xrow[i]) * w[i] * inv;
        orow[i] = __float2half_rn(t);
    }
}

// ---------------- RoPE in place on qk buffer ----------------
__global__ __launch_bounds__(128) void rope_kernel(
    float* __restrict__ qkbuf, const float* __restrict__ freqs,
    const int* __restrict__ positions)
{
    int mh = blockIdx.x;
    int m = mh / NHh, h = mh % NHh;
    int pos = positions[m];
    int t = threadIdx.x;
    int isK = t >> 6;
    int d = t & 63;

    size_t base = (size_t)m * QKW + (size_t)h * 256 + (size_t)isK * 128;
    float f1 = freqs[(size_t)pos * HDd + d];
    float f2 = freqs[(size_t)pos * HDd + d + 64];
    float c1 = cosf(f1), s1 = sinf(f1);
    float c2 = cosf(f2), s2 = sinf(f2);
    float x1 = qkbuf[base + d];
    float x2 = qkbuf[base + d + 64];
    qkbuf[base + d]      = x1 * c1 - x2 * s1;
    qkbuf[base + d + 64] = x2 * c2 + x1 * s2;
}

// ---------------- tensor-core causal flash attention (mma.sync tf32) ----------------
#define FTQ 128
#define FTK 32
#define FPD 132
#define FPP 36
#define FQ_SZ (FTQ * FPD)
#define FK_SZ (FTK * FPD)
#define FP_SZ (FTQ * FPP)
#define FSMEM_BYTES ((2 * FQ_SZ + 3 * FK_SZ + FP_SZ) * 4)

__global__ __launch_bounds__(256, 1) void flash_tc_kernel(
    const float* __restrict__ qkbuf, const float* __restrict__ vbuf,
    __half* __restrict__ attn16)
{
    extern __shared__ uint32_t fsm[];
    uint32_t* Qhi = fsm;
    uint32_t* Qlo = Qhi + FQ_SZ;
    uint32_t* Khi = Qlo + FQ_SZ;
    uint32_t* Klo = Khi + FK_SZ;
    uint32_t* Vs  = Klo + FK_SZ;
    uint32_t* Ps  = Vs  + FK_SZ;

    const int qt = gridDim.x - 1 - blockIdx.x;
    const int h  = blockIdx.y;
    const int b  = blockIdx.z;
    const int q0 = qt * FTQ;
    const int tid  = threadIdx.x;
    const int lane = tid & 31;
    const int warp = tid >> 5;
    const int wm16 = warp * 16;
    const int row4 = lane >> 2;
    const int col4 = lane & 3;
    const int bS = b * Ss;
    const int hq = h * 256;
    const float scale = 0.08838834764831845f;

    for (int c = tid; c < FTQ * 32; c += 256) {
        int row = c >> 5, colf = (c & 31) << 2;
        float4 q4 = *(const float4*)(qkbuf + (size_t)(bS + q0 + row) * QKW + hq + colf);
        uint4 hi, lo; float x;
        x = q4.x * scale; hi.x = f2tf(x); lo.x = f2tf(x - __uint_as_float(hi.x));
        x = q4.y * scale; hi.y = f2tf(x); lo.y = f2tf(x - __uint_as_float(hi.y));
        x = q4.z * scale; hi.z = f2tf(x); lo.z = f2tf(x - __uint_as_float(hi.z));
        x = q4.w * scale; hi.w = f2tf(x); lo.w = f2tf(x - __uint_as_float(hi.w));
        *(uint4*)&Qhi[row * FPD + colf] = hi;
        *(uint4*)&Qlo[row * FPD + colf] = lo;
    }

    float O[16][4];
#pragma unroll
    for (int ni = 0; ni < 16; ni++)
#pragma unroll
        for (int e = 0; e < 4; e++) O[ni][e] = 0.f;
    float mrow0 = -1e30f, mrow1 = -1e30f, lrow0 = 0.f, lrow1 = 0.f;

    const int kend = q0 + FTQ;
    for (int j0 = 0; j0 < kend; j0 += FTK) {
        __syncthreads();
        for (int c = tid; c < FTK * 32; c += 256) {
            int row = c >> 5, colf = (c & 31) << 2;
            float4 k4 = *(const float4*)(qkbuf + (size_t)(bS + j0 + row) * QKW + hq + 128 + colf);
            uint4 hi, lo;
            hi.x = f2tf(k4.x); lo.x = f2tf(k4.x - __uint_as_float(hi.x));
            hi.y = f2tf(k4.y); lo.y = f2tf(k4.y - __uint_as_float(hi.y));
            hi.z = f2tf(k4.z); lo.z = f2tf(k4.z - __uint_as_float(hi.z));
            hi.w = f2tf(k4.w); lo.w = f2tf(k4.w - __uint_as_float(hi.w));
            *(uint4*)&Khi[row * FPD + colf] = hi;
            *(uint4*)&Klo[row * FPD + colf] = lo;
            float4 v4 = *(const float4*)(vbuf + (size_t)(bS + j0 + row) * Pp + h * HDd + colf);
            uint4 vv;
            vv.x = f2tf(v4.x); vv.y = f2tf(v4.y); vv.z = f2tf(v4.z); vv.w = f2tf(v4.w);
            *(uint4*)&Vs[row * FPD + colf] = vv;
        }
        __syncthreads();

        bool active = (j0 <= q0 + wm16 + 15);
        if (active) {
            float s[4][4];
#pragma unroll
            for (int ni = 0; ni < 4; ni++)
#pragma unroll
                for (int e = 0; e < 4; e++) s[ni][e] = 0.f;

#pragma unroll
            for (int kk = 0; kk < HDd; kk += 8) {
                int ra = (wm16 + row4) * FPD + kk + col4;
                int rb8 = ra + 8 * FPD;
                uint32_t ahi[4] = {Qhi[ra], Qhi[rb8], Qhi[ra + 4], Qhi[rb8 + 4]};
                uint32_t alo[4] = {Qlo[ra], Qlo[rb8], Qlo[ra + 4], Qlo[rb8 + 4]};
#pragma unroll
                for (int ni = 0; ni < 4; ni++) {
                    int rn = (ni * 8 + row4) * FPD + kk + col4;
                    uint32_t bh[2] = {Khi[rn], Khi[rn + 4]};
                    uint32_t bl[2] = {Klo[rn], Klo[rn + 4]};
                    mma_tf32(s[ni], ahi, bh);
                    mma_tf32(s[ni], alo, bh);
                    mma_tf32(s[ni], ahi, bl);
                }
            }

            if (j0 + FTK - 1 > q0 + wm16) {
                int qlo = q0 + wm16 + row4;
                int qhi = qlo + 8;
#pragma unroll
                for (int ni = 0; ni < 4; ni++) {
                    int kp = j0 + ni * 8 + 2 * col4;
                    if (kp     > qlo) s[ni][0] = -1e30f;
                    if (kp + 1 > qlo) s[ni][1] = -1e30f;
                    if (kp     > qhi) s[ni][2] = -1e30f;
                    if (kp + 1 > qhi) s[ni][3] = -1e30f;
                }
            }

            float mx0 = -1e30f, mx1 = -1e30f;
#pragma unroll
            for (int ni = 0; ni < 4; ni++) {
                mx0 = fmaxf(mx0, fmaxf(s[ni][0], s[ni][1]));
                mx1 = fmaxf(mx1, fmaxf(s[ni][2], s[ni][3]));
            }
            mx0 = fmaxf(mx0, __shfl_xor_sync(0xffffffffu, mx0, 1));
            mx0 = fmaxf(mx0, __shfl_xor_sync(0xffffffffu, mx0, 2));
            mx1 = fmaxf(mx1, __shfl_xor_sync(0xffffffffu, mx1, 1));
            mx1 = fmaxf(mx1, __shfl_xor_sync(0xffffffffu, mx1, 2));
            float mn0 = fmaxf(mrow0, mx0), mn1 = fmaxf(mrow1, mx1);
            float al0 = __expf(mrow0 - mn0), al1 = __expf(mrow1 - mn1);
            mrow0 = mn0; mrow1 = mn1;

            float sum0 = 0.f, sum1 = 0.f;
            int pbase = (wm16 + row4) * FPP + 2 * col4;
#pragma unroll
            for (int ni = 0; ni < 4; ni++) {
                float p0 = __expf(s[ni][0] - mn0);
                float p1 = __expf(s[ni][1] - mn0);
                float p2 = __expf(s[ni][2] - mn1);
                float p3 = __expf(s[ni][3] - mn1);
                sum0 += p0 + p1; sum1 += p2 + p3;
                Ps[pbase + ni * 8]               = f2tf(p0);
                Ps[pbase + ni * 8 + 1]           = f2tf(p1);
                Ps[pbase + ni * 8 + 8 * FPP]     = f2tf(p2);
                Ps[pbase + ni * 8 + 8 * FPP + 1] = f2tf(p3);
            }
            lrow0 = lrow0 * al0 + sum0;
            lrow1 = lrow1 * al1 + sum1;
#pragma unroll
            for (int ni = 0; ni < 16; ni++) {
                O[ni][0] *= al0; O[ni][1] *= al0;
                O[ni][2] *= al1; O[ni][3] *= al1;
            }
            __syncwarp();

#pragma unroll
            for (int kp = 0; kp < FTK; kp += 8) {
                int pa = (wm16 + row4) * FPP + kp + col4;
                uint32_t a[4] = {Ps[pa], Ps[pa + 8 * FPP], Ps[pa + 4], Ps[pa + 8 * FPP + 4]};
#pragma unroll
                for (int ni = 0; ni < 16; ni++) {
                    int vb = (kp + col4) * FPD + ni * 8 + row4;
                    uint32_t bv[2] = {Vs[vb], Vs[vb + 4 * FPD]};
                    mma_tf32(O[ni], a, bv);
                }
            }
        }
    }

    lrow0 += __shfl_xor_sync(0xffffffffu, lrow0, 1);
    lrow0 += __shfl_xor_sync(0xffffffffu, lrow0, 2);
    lrow1 += __shfl_xor_sync(0xffffffffu, lrow1, 1);
    lrow1 += __shfl_xor_sync(0xffffffffu, lrow1, 2);
    float inv0 = 1.f / lrow0, inv1 = 1.f / lrow1;

    size_t ob0 = (size_t)(bS + q0 + wm16 + row4) * Pp + h * HDd;
    size_t ob1 = ob0 + (size_t)8 * Pp;
#pragma unroll
    for (int ni = 0; ni < 16; ni++) {
        int cb = ni * 8 + 2 * col4;
        *(uint32_t*)(attn16 + ob0 + cb) = h2pack(O[ni][0] * inv0, O[ni][1] * inv0);
        *(uint32_t*)(attn16 + ob1 + cb) = h2pack(O[ni][2] * inv1, O[ni][3] * inv1);
    }
}

// ---------------- tail outputs ----------------
__global__ void tails_kernel(const float* __restrict__ hs, const float* __restrict__ y1,
                             float* __restrict__ out)
{
    int i = blockIdx.x * 256 + threadIdx.x;
    size_t off1 = (size_t)Mm * Hh;
    size_t off2 = off1 + (size_t)Bb * Hh;
    if (i < Bb * Hh) {
        int b = i / Hh, hh = i % Hh;
        out[off1 + i] = hs[((size_t)b * Ss + (Ss - 1)) * Hh + hh];
    }
    if (i < Bb * H2) {
        int b = i / H2, oo = i % H2;
        out[off2 + i] = y1[((size_t)b * Ss + (Ss - 1)) * H2 + oo];
    }
}

// ---------------- launch ----------------
extern "C" void kernel_launch(void* const* d_in, const int* in_sizes, int n_in,
                              void* d_out, int out_size)
{
    (void)in_sizes; (void)n_in; (void)out_size;
    const float* hs      = (const float*)d_in[0];
    const float* freqs   = (const float*)d_in[1];
    const int*   pos     = (const int*)  d_in[2];
    const float* Wqk     = (const float*)d_in[3];
    const float* Wv      = (const float*)d_in[4];
    const float* Wo      = (const float*)d_in[5];
    const float* conv1_w = (const float*)d_in[6];
    const float* conv1_b = (const float*)d_in[7];
    const float* conv2_w = (const float*)d_in[8];
    const float* conv2_b = (const float*)d_in[9];
    const float* ln_w    = (const float*)d_in[10];
    const float* lf1c    = (const float*)d_in[11];
    const float* lf2c    = (const float*)d_in[12];
    float* out = (float*)d_out;

    float *v, *y1, *lfout, *qk;
    __half *hs16, *wv16, *wqk16, *wo16, *w1a16, *w1b16, *w2a16, *w2b16;
    __half *y1h, *lf16, *attn16, *lf1c16, *lf2c16;
    cudaGetSymbolAddress((void**)&v,      g_v);
    cudaGetSymbolAddress((void**)&y1,     g_y1);
    cudaGetSymbolAddress((void**)&lfout,  g_lfout);
    cudaGetSymbolAddress((void**)&qk,     g_qk);
    cudaGetSymbolAddress((void**)&hs16,   g_hs16);
    cudaGetSymbolAddress((void**)&wv16,   g_wv16);
    cudaGetSymbolAddress((void**)&wqk16,  g_wqk16);
    cudaGetSymbolAddress((void**)&wo16,   g_wo16);
    cudaGetSymbolAddress((void**)&w1a16,  g_w1a16);
    cudaGetSymbolAddress((void**)&w1b16,  g_w1b16);
    cudaGetSymbolAddress((void**)&w2a16,  g_w2a16);
    cudaGetSymbolAddress((void**)&w2b16,  g_w2b16);
    cudaGetSymbolAddress((void**)&y1h,    g_y1h);
    cudaGetSymbolAddress((void**)&lf16,   g_lf16);
    cudaGetSymbolAddress((void**)&attn16, g_attn16);
    cudaGetSymbolAddress((void**)&lf1c16, g_lf1c16);
    cudaGetSymbolAddress((void**)&lf2c16, g_lf2c16);

    static bool attr_done = false;
    if (!attr_done) {
        cudaFuncSetAttribute(flash_tc_kernel,
                             cudaFuncAttributeMaxDynamicSharedMemorySize, FSMEM_BYTES);
        cudaFuncSetAttribute(gemm_h16_kernel,
                             cudaFuncAttributeMaxDynamicSharedMemorySize, GH_SMEM);
        attr_done = true;
    }

    // 1) conversions + weight deinterleave (fp16 operand prep)
    cvt16_kernel<<<(Mm * Hh / 8 + 255) / 256, 256>>>(hs, hs16, Mm * Hh);
    cvt16_kernel<<<(Pp * Hh / 8 + 255) / 256, 256>>>(Wv, wv16, Pp * Hh);
    cvt16_kernel<<<(QKW * Hh / 8 + 255) / 256, 256>>>(Wqk, wqk16, QKW * Hh);
    cvt16_kernel<<<(Hh * Pp / 8 + 255) / 256, 256>>>(Wo, wo16, Hh * Pp);
    cvt16_kernel<<<(Bb * Hh / 8 + 255) / 256, 256>>>(lf1c, lf1c16, Bb * Hh);
    cvt16_kernel<<<(Bb * H2 / 8 + 255) / 256, 256>>>(lf2c, lf2c16, Bb * H2);
    deint16_kernel<<<(H2 * Hh + 255) / 256, 256>>>(conv1_w, w1a16, w1b16, H2 * Hh);
    deint16_kernel<<<(Hh * H2 + 255) / 256, 256>>>(conv2_w, w2a16, w2b16, Hh * H2);

    // 2) v = hs @ Wv^T  (fp32 out for flash)
    gemm_h16_kernel<<<dim3(Pp / BNh, Mm / BMh), 256, GH_SMEM>>>(
        hs16, wv16, nullptr, nullptr, v, nullptr, Pp, Hh, nullptr, nullptr);

    // 3) y1 = shift(hs) @ w1a^T + hs @ w1b^T + b1  (fp32 + fp16 mirror)
    gemm_h16_kernel<<<dim3(H2 / BNh, Mm / BMh), 256, GH_SMEM>>>(
        hs16, w1a16, hs16, w1b16, y1, y1h, H2, Hh, conv1_b, lf1c16);

    // 4) y2 = shift(y1) @ w2a^T + y1 @ w2b^T + b2  (fp32 only)
    gemm_h16_kernel<<<dim3(Hh / BNh, Mm / BMh), 256, GH_SMEM>>>(
        y1h, w2a16, y1h, w2b16, lfout, nullptr, Hh, H2, conv2_b, lf2c16);

    // 5) lf16 = rmsnorm(y2 + hs) * ln_w   (fp16 out)
    rmsnorm_kernel<<<Mm, 256>>>(lfout, hs, ln_w, lf16);

    // 6) qk = lf16 @ Wqk^T  (fp32 out for rope/flash)
    gemm_h16_kernel<<<dim3(QKW / BNh, Mm / BMh), 256, GH_SMEM>>>(
        lf16, wqk16, nullptr, nullptr, qk, nullptr, QKW, Hh, nullptr, nullptr);

    // 7) RoPE in place
    rope_kernel<<<Mm * NHh, 128>>>(qk, freqs, pos);

    // 8) flash attention -> attn16 (fp16)
    flash_tc_kernel<<<dim3(Ss / FTQ, NHh, Bb), 256, FSMEM_BYTES>>>(qk, v, attn16);

    // 9) output = attn16 @ Wo^T  (fp32 out)
    gemm_h16_kernel<<<dim3(Hh / BNh, Mm / BMh), 256, GH_SMEM>>>(
        attn16, wo16, nullptr, nullptr, out, nullptr, Hh, Pp, nullptr, nullptr);

    // 10) tails
    tails_kernel<<<(Bb * Hh + 255) / 256, 256>>>(hs, y1, out);
}

// round 13
// speedup vs baseline: 1.8897x; 1.1965x over previous
#include <cuda_runtime.h>
#include <cuda_fp16.h>
#include <cuda_bf16.h>
#include <cstdint>
#include <cstddef>

// Problem constants
#define Bb   2
#define Ss   2048
#define Hh   2048
#define NHh  16
#define HDd  128
#define Pp   2048
#define Mm   (Bb * Ss)          // 4096 rows
#define H2   (Hh / 2)           // 1024
#define QKW  (2 * Pp)           // 4096 (qk row width)
#define MW16 (NHh * HDd)        // 2048 (fp16 q/k buffer row width)
#define EPSc 1e-6f

// ---------------- scratch (static device globals; no allocation) ----------------
// fp32
__device__ float g_y1[(size_t)Mm * H2];
__device__ float g_lfout[(size_t)Mm * Hh];     // y2 (pre-rmsnorm)
__device__ float g_qk[(size_t)Mm * QKW];
// fp16 operands
__device__ __half g_hs16[(size_t)Mm * Hh];
__device__ __half g_wv16[(size_t)Pp * Hh];
__device__ __half g_wqk16[(size_t)QKW * Hh];
__device__ __half g_wo16[(size_t)Hh * Pp];
__device__ __half g_w1a16[(size_t)H2 * Hh];
__device__ __half g_w1b16[(size_t)H2 * Hh];
__device__ __half g_w2a16[(size_t)Hh * H2];
__device__ __half g_w2b16[(size_t)Hh * H2];
__device__ __half g_y1h[(size_t)Mm * H2];
__device__ __half g_lf16[(size_t)Mm * Hh];
__device__ __half g_v16[(size_t)Mm * Pp];
__device__ __half g_attn16[(size_t)Mm * Pp];
__device__ __half g_lf1c16[(size_t)Bb * Hh];
__device__ __half g_lf2c16[(size_t)Bb * H2];
// rope outputs (fp16 hi/lo)
__device__ __half g_qhi[(size_t)Mm * MW16];
__device__ __half g_qlo[(size_t)Mm * MW16];
__device__ __half g_khi[(size_t)Mm * MW16];
__device__ __half g_klo[(size_t)Mm * MW16];

// ---------------- helpers ----------------
__device__ __forceinline__ void mma_f16(float* d, const uint32_t* a, const uint32_t* b) {
    asm volatile(
        "mma.sync.aligned.m16n8k16.row.col.f32.f16.f16.f32 "
        "{%0,%1,%2,%3},{%4,%5,%6,%7},{%8,%9},{%0,%1,%2,%3};"
        : "+f"(d[0]), "+f"(d[1]), "+f"(d[2]), "+f"(d[3])
        : "r"(a[0]), "r"(a[1]), "r"(a[2]), "r"(a[3]), "r"(b[0]), "r"(b[1]));
}

__device__ __forceinline__ uint32_t h2pack(float lo, float hi) {
    __half2 h = __floats2half2_rn(lo, hi);
    return *reinterpret_cast<uint32_t*>(&h);
}

__device__ __forceinline__ void cp16(uint32_t* smem, const void* g) {
    uint32_t s = (uint32_t)__cvta_generic_to_shared(smem);
    asm volatile("cp.async.ca.shared.global [%0], [%1], 16;" :: "r"(s), "l"(g));
}

// ---------------- fp32 -> fp16 conversion (8 elts/thread) ----------------
__global__ void cvt16_kernel(const float* __restrict__ in, __half* __restrict__ out, int n)
{
    int i = (blockIdx.x * 256 + threadIdx.x) * 8;
    if (i < n) {
        float4 f0 = *(const float4*)(in + i);
        float4 f1 = *(const float4*)(in + i + 4);
        uint4 u;
        u.x = h2pack(f0.x, f0.y); u.y = h2pack(f0.z, f0.w);
        u.z = h2pack(f1.x, f1.y); u.w = h2pack(f1.z, f1.w);
        *(uint4*)(out + i) = u;
    }
}

// ---------------- deinterleave conv weights -> fp16 ----------------
__global__ void deint16_kernel(const float* __restrict__ in, __half* __restrict__ a,
                               __half* __restrict__ b, int n)
{
    int i = blockIdx.x * 256 + threadIdx.x;
    if (i < n) {
        a[i] = __float2half_rn(in[2 * i]);
        b[i] = __float2half_rn(in[2 * i + 1]);
    }
}

// ========== FP16 tensor-core GEMM (NT), cp.async 4-stage pipeline ==========
// (validated in R12; C made optional this round)
#define BMh 128
#define BNh 128
#define BKh 32
#define PWH 20
#define NSTG 4
#define STG_W (BMh * PWH)
#define GH_SMEM (NSTG * STG_W * 2 * 4)         // 81920 bytes

__global__ __launch_bounds__(256, 2) void gemm_h16_kernel(
    const __half* __restrict__ A, const __half* __restrict__ W,
    const __half* __restrict__ A2, const __half* __restrict__ W2,
    float* __restrict__ C, __half* __restrict__ C16,
    int N, int K, const float* __restrict__ bias,
    const __half* __restrict__ shiftCache)
{
    extern __shared__ uint32_t sh[];
    uint32_t* Abase = sh;
    uint32_t* Bbase = sh + NSTG * STG_W;

    const int tid = threadIdx.x;
    const int lane = tid & 31;
    const int warp = tid >> 5;
    const int wm = warp >> 2;
    const int wn = warp & 3;
    const int bm = blockIdx.y * BMh;
    const int bn = blockIdx.x * BNh;
    const int mBase = wm * 64;
    const int nBase = wn * 32;

    const int ra = tid >> 1;
    const int seg = tid & 1;
    const int sk = seg * 16;
    const int sw = seg * 8;

    const __half* arow;
    {
        int m = bm + ra;
        if (shiftCache) {
            arow = (m % Ss == 0) ? (shiftCache + (size_t)(m / Ss) * K)
                                 : (A + (size_t)(m - 1) * K);
        } else {
            arow = A + (size_t)m * K;
        }
    }
    const __half* wrow  = W + (size_t)(bn + ra) * K;
    const __half* a2row = A2 ? (A2 + (size_t)(bm + ra) * K) : nullptr;
    const __half* w2row = W2 ? (W2 + (size_t)(bn + ra) * K) : nullptr;

    float acc[4][4][4];
#pragma unroll
    for (int mi = 0; mi < 4; mi++)
#pragma unroll
        for (int ni = 0; ni < 4; ni++)
#pragma unroll
            for (int e = 0; e < 4; e++) acc[mi][ni][e] = 0.f;

    const int nk = K / BKh;
    const int nkt = A2 ? (2 * nk) : nk;

    auto issue = [&](int kt) {
        const __half* ap;
        const __half* wp;
        if (kt < nk) { ap = arow  + kt * BKh + sk;        wp = wrow  + kt * BKh + sk; }
        else         { ap = a2row + (kt - nk) * BKh + sk; wp = w2row + (kt - nk) * BKh + sk; }
        uint32_t* as = Abase + (kt % NSTG) * STG_W + ra * PWH + sw;
        uint32_t* bs = Bbase + (kt % NSTG) * STG_W + ra * PWH + sw;
        cp16(as,     ap);
        cp16(as + 4, ap + 8);
        cp16(bs,     wp);
        cp16(bs + 4, wp + 8);
    };

#pragma unroll
    for (int s = 0; s < NSTG - 1; s++) {
        if (s < nkt) issue(s);
        asm volatile("cp.async.commit_group;");
    }

    const int row4 = lane >> 2;
    const int col4 = lane & 3;

    for (int kt = 0; kt < nkt; kt++) {
        asm volatile("cp.async.wait_group %0;" :: "n"(NSTG - 2));
        __syncthreads();

        if (kt + NSTG - 1 < nkt) issue(kt + NSTG - 1);
        asm volatile("cp.async.commit_group;");

        const uint32_t* as = Abase + (kt % NSTG) * STG_W;
        const uint32_t* bs = Bbase + (kt % NSTG) * STG_W;
#pragma unroll
        for (int kw = 0; kw < 16; kw += 8) {
            uint32_t af[4][4], bf[4][2];
#pragma unroll
            for (int mi = 0; mi < 4; mi++) {
                int m0 = mBase + mi * 16;
                af[mi][0] = as[(m0 + row4) * PWH + kw + col4];
                af[mi][1] = as[(m0 + row4 + 8) * PWH + kw + col4];
                af[mi][2] = as[(m0 + row4) * PWH + kw + col4 + 4];
                af[mi][3] = as[(m0 + row4 + 8) * PWH + kw + col4 + 4];
            }
#pragma unroll
            for (int ni = 0; ni < 4; ni++) {
                int n0 = nBase + ni * 8;
                bf[ni][0] = bs[(n0 + row4) * PWH + kw + col4];
                bf[ni][1] = bs[(n0 + row4) * PWH + kw + col4 + 4];
            }
#pragma unroll
            for (int mi = 0; mi < 4; mi++)
#pragma unroll
                for (int ni = 0; ni < 4; ni++)
                    mma_f16(acc[mi][ni], af[mi], bf[ni]);
        }
    }

#pragma unroll
    for (int mi = 0; mi < 4; mi++) {
        int r = bm + mBase + mi * 16 + row4;
#pragma unroll
        for (int ni = 0; ni < 4; ni++) {
            int cb = bn + nBase + ni * 8 + 2 * col4;
            float2 b2 = make_float2(0.f, 0.f);
            if (bias) { b2.x = bias[cb]; b2.y = bias[cb + 1]; }
            float2 v0 = make_float2(acc[mi][ni][0] + b2.x, acc[mi][ni][1] + b2.y);
            float2 v1 = make_float2(acc[mi][ni][2] + b2.x, acc[mi][ni][3] + b2.y);
            if (C) {
                *(float2*)(C + (size_t)r * N + cb) = v0;
                *(float2*)(C + (size_t)(r + 8) * N + cb) = v1;
            }
            if (C16) {
                *(uint32_t*)(C16 + (size_t)r * N + cb) = h2pack(v0.x, v0.y);
                *(uint32_t*)(C16 + (size_t)(r + 8) * N + cb) = h2pack(v1.x, v1.y);
            }
        }
    }
}

// ---------------- residual add + RMSNorm -> fp16 output ----------------
__global__ __launch_bounds__(256) void rmsnorm_kernel(
    const float* __restrict__ y2, const float* __restrict__ x,
    const float* __restrict__ w, __half* __restrict__ out16)
{
    int m = blockIdx.x;
    const float* yrow = y2 + (size_t)m * Hh;
    const float* xrow = x + (size_t)m * Hh;

    float ss = 0.f;
    for (int i = threadIdx.x; i < Hh; i += 256) {
        float t = yrow[i] + xrow[i];
        ss += t * t;
    }
#pragma unroll
    for (int off = 16; off > 0; off >>= 1)
        ss += __shfl_xor_sync(0xffffffffu, ss, off);

    __shared__ float red[9];
    int lane = threadIdx.x & 31, wid = threadIdx.x >> 5;
    if (lane == 0) red[wid] = ss;
    __syncthreads();
    if (threadIdx.x == 0) {
        float tot = 0.f;
        for (int i = 0; i < 8; i++) tot += red[i];
        red[8] = rsqrtf(tot / (float)Hh + EPSc);
    }
    __syncthreads();
    float inv = red[8];
    __half* orow = out16 + (size_t)m * Hh;
    for (int i = threadIdx.x; i < Hh; i += 256) {
        float t = (yrow[i] + xrow[i]) * w[i] * inv;
        orow[i] = __float2half_rn(t);
    }
}

// ---------------- RoPE: qk fp32 -> fp16 hi/lo buffers (Q scaled) ----------------
__global__ __launch_bounds__(128) void rope2_kernel(
    const float* __restrict__ qkbuf, const float* __restrict__ freqs,
    const int* __restrict__ positions,
    __half* __restrict__ qhi, __half* __restrict__ qlo,
    __half* __restrict__ khi, __half* __restrict__ klo)
{
    int mh = blockIdx.x;
    int m = mh / NHh, h = mh % NHh;
    int pos = positions[m];
    int t = threadIdx.x;
    int isK = t >> 6;
    int d = t & 63;

    size_t base = (size_t)m * QKW + (size_t)h * 256 + (size_t)isK * 128;
    float f1 = freqs[(size_t)pos * HDd + d];
    float f2 = freqs[(size_t)pos * HDd + d + 64];
    float c1 = cosf(f1), s1 = sinf(f1);
    float c2 = cosf(f2), s2 = sinf(f2);
    float x1 = qkbuf[base + d];
    float x2 = qkbuf[base + d + 64];
    float r1 = x1 * c1 - x2 * s1;
    float r2 = x2 * c2 + x1 * s2;

    const float scale = 0.08838834764831845f;   // 1/sqrt(128)
    size_t o = (size_t)m * MW16 + (size_t)h * HDd + d;
    if (isK == 0) {
        float a1 = r1 * scale, a2 = r2 * scale;
        __half h1 = __float2half_rn(a1);
        __half h2 = __float2half_rn(a2);
        qhi[o]      = h1;  qlo[o]      = __float2half_rn(a1 - __half2float(h1));
        qhi[o + 64] = h2;  qlo[o + 64] = __float2half_rn(a2 - __half2float(h2));
    } else {
        __half h1 = __float2half_rn(r1);
        __half h2 = __float2half_rn(r2);
        khi[o]      = h1;  klo[o]      = __float2half_rn(r1 - __half2float(h1));
        khi[o + 64] = h2;  klo[o + 64] = __float2half_rn(r2 - __half2float(h2));
    }
}

// ---------------- fp16 tensor-core causal flash attention ----------------
// TQ=128 (8 warps x 16 rows), TK=32. QK = 3x fp16 hi/lo, PV = fp16.
// cp.async staging of pre-converted Q/K; V transpose-staged from fp16 mirror.
#define F2Q 128
#define F2K 32
#define PQ 68    // words per Q/K smem row (64 data + 4 pad); bank-clean
#define PV 20    // words per Vt/Ps smem row (16 data + 4 pad); bank-clean
#define Q_SZ (F2Q * PQ)          // 8704 words
#define K_SZ (F2K * PQ)          // 2176 words
#define T_SZ (F2Q * PV)          // 2560 words
#define F2_SMEM ((2 * Q_SZ + 2 * K_SZ + 2 * T_SZ) * 4)   // 107520 bytes

__global__ __launch_bounds__(256, 2) void flash2_kernel(
    const __half* __restrict__ qhi_g, const __half* __restrict__ qlo_g,
    const __half* __restrict__ khi_g, const __half* __restrict__ klo_g,
    const __half* __restrict__ v16, __half* __restrict__ attn16)
{
    extern __shared__ uint32_t fsm[];
    uint32_t* Qhi = fsm;
    uint32_t* Qlo = Qhi + Q_SZ;
    uint32_t* Khi = Qlo + Q_SZ;
    uint32_t* Klo = Khi + K_SZ;
    uint32_t* Vt  = Klo + K_SZ;      // transposed V: [d][kv]
    uint32_t* Ps  = Vt  + T_SZ;
    __half* VtH = (__half*)Vt;

    const int qt = gridDim.x - 1 - blockIdx.x;   // heavy tiles first
    const int h  = blockIdx.y;
    const int b  = blockIdx.z;
    const int q0 = qt * F2Q;
    const int tid  = threadIdx.x;
    const int lane = tid & 31;
    const int warp = tid >> 5;
    const int wm16 = warp * 16;
    const int row4 = lane >> 2;
    const int col4 = lane & 3;
    const int bS = b * Ss;
    const int hq = h * HDd;

    // ---- stage Q (hi+lo), cp.async ----
    for (int c = tid; c < F2Q * 16; c += 256) {
        int row = c >> 4, ch = c & 15;
        size_t g = (size_t)(bS + q0 + row) * MW16 + hq + ch * 8;
        cp16(Qhi + row * PQ + ch * 4, qhi_g + g);
        cp16(Qlo + row * PQ + ch * 4, qlo_g + g);
    }
    asm volatile("cp.async.commit_group;");

    float O[16][4];
#pragma unroll
    for (int ni = 0; ni < 16; ni++)
#pragma unroll
        for (int e = 0; e < 4; e++) O[ni][e] = 0.f;
    float mrow0 = -1e30f, mrow1 = -1e30f, lrow0 = 0.f, lrow1 = 0.f;

    const int kend = q0 + F2Q;
    for (int j0 = 0; j0 < kend; j0 += F2K) {
        __syncthreads();   // prior compute done before K/V/Ps overwrite
        // K hi/lo via cp.async
        for (int c = tid; c < F2K * 16; c += 256) {
            int row = c >> 4, ch = c & 15;
            size_t g = (size_t)(bS + j0 + row) * MW16 + hq + ch * 8;
            cp16(Khi + row * PQ + ch * 4, khi_g + g);
            cp16(Klo + row * PQ + ch * 4, klo_g + g);
        }
        asm volatile("cp.async.commit_group;");
        // V transpose staging (fp16 gmem [kv][d] -> smem [d][kv])
        for (int c = tid; c < F2K * 16; c += 256) {
            int kv = c >> 4, d0 = (c & 15) * 8;
            uint4 u = *(const uint4*)(v16 + (size_t)(bS + j0 + kv) * Pp + hq + d0);
            const __half* hp = (const __half*)&u;
#pragma unroll
            for (int j = 0; j < 8; j++)
                VtH[(d0 + j) * (2 * PV) + kv] = hp[j];
        }
        asm volatile("cp.async.wait_group 0;");
        __syncthreads();

        bool active = (j0 <= q0 + wm16 + 15);   // warp-uniform
        if (active) {
            // ---- S = Q K^T (3x fp16 hi/lo) ----
            float s[4][4];
#pragma unroll
            for (int ni = 0; ni < 4; ni++)
#pragma unroll
                for (int e = 0; e < 4; e++) s[ni][e] = 0.f;

#pragma unroll
            for (int kw = 0; kw < 64; kw += 8) {     // 8 k16 steps over 128 dims
                int raq = (wm16 + row4) * PQ + kw + col4;
                int rb8 = raq + 8 * PQ;
                uint32_t ahi[4] = {Qhi[raq], Qhi[rb8], Qhi[raq + 4], Qhi[rb8 + 4]};
                uint32_t alo[4] = {Qlo[raq], Qlo[rb8], Qlo[raq + 4], Qlo[rb8 + 4]};
#pragma unroll
                for (int ni = 0; ni < 4; ni++) {
                    int rn = (ni * 8 + row4) * PQ + kw + col4;
                    uint32_t bh[2] = {Khi[rn], Khi[rn + 4]};
                    uint32_t bl[2] = {Klo[rn], Klo[rn + 4]};
                    mma_f16(s[ni], ahi, bh);
                    mma_f16(s[ni], alo, bh);
                    mma_f16(s[ni], ahi, bl);
                }
            }

            // ---- causal mask ----
            if (j0 + F2K - 1 > q0 + wm16) {
                int qlo_i = q0 + wm16 + row4;
                int qhi_i = qlo_i + 8;
#pragma unroll
                for (int ni = 0; ni < 4; ni++) {
                    int kp = j0 + ni * 8 + 2 * col4;
                    if (kp     > qlo_i) s[ni][0] = -1e30f;
                    if (kp + 1 > qlo_i) s[ni][1] = -1e30f;
                    if (kp     > qhi_i) s[ni][2] = -1e30f;
                    if (kp + 1 > qhi_i) s[ni][3] = -1e30f;
                }
            }

            // ---- online softmax ----
            float mx0 = -1e30f, mx1 = -1e30f;
#pragma unroll
            for (int ni = 0; ni < 4; ni++) {
                mx0 = fmaxf(mx0, fmaxf(s[ni][0], s[ni][1]));
                mx1 = fmaxf(mx1, fmaxf(s[ni][2], s[ni][3]));
            }
            mx0 = fmaxf(mx0, __shfl_xor_sync(0xffffffffu, mx0, 1));
            mx0 = fmaxf(mx0, __shfl_xor_sync(0xffffffffu, mx0, 2));
            mx1 = fmaxf(mx1, __shfl_xor_sync(0xffffffffu, mx1, 1));
            mx1 = fmaxf(mx1, __shfl_xor_sync(0xffffffffu, mx1, 2));
            float mn0 = fmaxf(mrow0, mx0), mn1 = fmaxf(mrow1, mx1);
            float al0 = __expf(mrow0 - mn0), al1 = __expf(mrow1 - mn1);
            mrow0 = mn0; mrow1 = mn1;

            float sum0 = 0.f, sum1 = 0.f;
            int pb0 = (wm16 + row4) * PV;
            int pb1 = (wm16 + row4 + 8) * PV;
#pragma unroll
            for (int ni = 0; ni < 4; ni++) {
                float p0 = __expf(s[ni][0] - mn0);
                float p1 = __expf(s[ni][1] - mn0);
                float p2 = __expf(s[ni][2] - mn1);
                float p3 = __expf(s[ni][3] - mn1);
                sum0 += p0 + p1; sum1 += p2 + p3;
                Ps[pb0 + ni * 4 + col4] = h2pack(p0, p1);
                Ps[pb1 + ni * 4 + col4] = h2pack(p2, p3);
            }
            lrow0 = lrow0 * al0 + sum0;
            lrow1 = lrow1 * al1 + sum1;
#pragma unroll
            for (int ni = 0; ni < 16; ni++) {
                O[ni][0] *= al0; O[ni][1] *= al0;
                O[ni][2] *= al1; O[ni][3] *= al1;
            }
            __syncwarp();   // Ps rows warp-private

            // ---- O += P V  (fp16, V transposed in smem) ----
#pragma unroll
            for (int kw = 0; kw < 16; kw += 8) {     // 2 k16 steps over 32 keys
                int pa = (wm16 + row4) * PV + kw + col4;
                uint32_t a[4] = {Ps[pa], Ps[pa + 8 * PV], Ps[pa + 4], Ps[pa + 8 * PV + 4]};
#pragma unroll
                for (int ni = 0; ni < 16; ni++) {
                    int vb = (ni * 8 + row4) * PV + kw + col4;
                    uint32_t bv[2] = {Vt[vb], Vt[vb + 4]};
                    mma_f16(O[ni], a, bv);
                }
            }
        }
    }

    // ---- finalize ----
    lrow0 += __shfl_xor_sync(0xffffffffu, lrow0, 1);
    lrow0 += __shfl_xor_sync(0xffffffffu, lrow0, 2);
    lrow1 += __shfl_xor_sync(0xffffffffu, lrow1, 1);
    lrow1 += __shfl_xor_sync(0xffffffffu, lrow1, 2);
    float inv0 = 1.f / lrow0, inv1 = 1.f / lrow1;

    size_t ob0 = (size_t)(bS + q0 + wm16 + row4) * Pp + hq;
    size_t ob1 = ob0 + (size_t)8 * Pp;
#pragma unroll
    for (int ni = 0; ni < 16; ni++) {
        int cb = ni * 8 + 2 * col4;
        *(uint32_t*)(attn16 + ob0 + cb) = h2pack(O[ni][0] * inv0, O[ni][1] * inv0);
        *(uint32_t*)(attn16 + ob1 + cb) = h2pack(O[ni][2] * inv1, O[ni][3] * inv1);
    }
}

// ---------------- tail outputs ----------------
__global__ void tails_kernel(const float* __restrict__ hs, const float* __restrict__ y1,
                             float* __restrict__ out)
{
    int i = blockIdx.x * 256 + threadIdx.x;
    size_t off1 = (size_t)Mm * Hh;
    size_t off2 = off1 + (size_t)Bb * Hh;
    if (i < Bb * Hh) {
        int b = i / Hh, hh = i % Hh;
        out[off1 + i] = hs[((size_t)b * Ss + (Ss - 1)) * Hh + hh];
    }
    if (i < Bb * H2) {
        int b = i / H2, oo = i % H2;
        out[off2 + i] = y1[((size_t)b * Ss + (Ss - 1)) * H2 + oo];
    }
}

// ---------------- launch ----------------
extern "C" void kernel_launch(void* const* d_in, const int* in_sizes, int n_in,
                              void* d_out, int out_size)
{
    (void)in_sizes; (void)n_in; (void)out_size;
    const float* hs      = (const float*)d_in[0];
    const float* freqs   = (const float*)d_in[1];
    const int*   pos     = (const int*)  d_in[2];
    const float* Wqk     = (const float*)d_in[3];
    const float* Wv      = (const float*)d_in[4];
    const float* Wo      = (const float*)d_in[5];
    const float* conv1_w = (const float*)d_in[6];
    const float* conv1_b = (const float*)d_in[7];
    const float* conv2_w = (const float*)d_in[8];
    const float* conv2_b = (const float*)d_in[9];
    const float* ln_w    = (const float*)d_in[10];
    const float* lf1c    = (const float*)d_in[11];
    const float* lf2c    = (const float*)d_in[12];
    float* out = (float*)d_out;

    float *y1, *lfout, *qk;
    __half *hs16, *wv16, *wqk16, *wo16, *w1a16, *w1b16, *w2a16, *w2b16;
    __half *y1h, *lf16, *v16, *attn16, *lf1c16, *lf2c16;
    __half *qhi, *qlo, *khi, *klo;
    cudaGetSymbolAddress((void**)&y1,     g_y1);
    cudaGetSymbolAddress((void**)&lfout,  g_lfout);
    cudaGetSymbolAddress((void**)&qk,     g_qk);
    cudaGetSymbolAddress((void**)&hs16,   g_hs16);
    cudaGetSymbolAddress((void**)&wv16,   g_wv16);
    cudaGetSymbolAddress((void**)&wqk16,  g_wqk16);
    cudaGetSymbolAddress((void**)&wo16,   g_wo16);
    cudaGetSymbolAddress((void**)&w1a16,  g_w1a16);
    cudaGetSymbolAddress((void**)&w1b16,  g_w1b16);
    cudaGetSymbolAddress((void**)&w2a16,  g_w2a16);
    cudaGetSymbolAddress((void**)&w2b16,  g_w2b16);
    cudaGetSymbolAddress((void**)&y1h,    g_y1h);
    cudaGetSymbolAddress((void**)&lf16,   g_lf16);
    cudaGetSymbolAddress((void**)&v16,    g_v16);
    cudaGetSymbolAddress((void**)&attn16, g_attn16);
    cudaGetSymbolAddress((void**)&lf1c16, g_lf1c16);
    cudaGetSymbolAddress((void**)&lf2c16, g_lf2c16);
    cudaGetSymbolAddress((void**)&qhi,    g_qhi);
    cudaGetSymbolAddress((void**)&qlo,    g_qlo);
    cudaGetSymbolAddress((void**)&khi,    g_khi);
    cudaGetSymbolAddress((void**)&klo,    g_klo);

    static bool attr_done = false;
    if (!attr_done) {
        cudaFuncSetAttribute(flash2_kernel,
                             cudaFuncAttributeMaxDynamicSharedMemorySize, F2_SMEM);
        cudaFuncSetAttribute(gemm_h16_kernel,
                             cudaFuncAttributeMaxDynamicSharedMemorySize, GH_SMEM);
        attr_done = true;
    }

    // 1) fp16 operand prep
    cvt16_kernel<<<(Mm * Hh / 8 + 255) / 256, 256>>>(hs, hs16, Mm * Hh);
    cvt16_kernel<<<(Pp * Hh / 8 + 255) / 256, 256>>>(Wv, wv16, Pp * Hh);
    cvt16_kernel<<<(QKW * Hh / 8 + 255) / 256, 256>>>(Wqk, wqk16, QKW * Hh);
    cvt16_kernel<<<(Hh * Pp / 8 + 255) / 256, 256>>>(Wo, wo16, Hh * Pp);
    cvt16_kernel<<<(Bb * Hh / 8 + 255) / 256, 256>>>(lf1c, lf1c16, Bb * Hh);
    cvt16_kernel<<<(Bb * H2 / 8 + 255) / 256, 256>>>(lf2c, lf2c16, Bb * H2);
    deint16_kernel<<<(H2 * Hh + 255) / 256, 256>>>(conv1_w, w1a16, w1b16, H2 * Hh);
    deint16_kernel<<<(Hh * H2 + 255) / 256, 256>>>(conv2_w, w2a16, w2b16, Hh * H2);

    // 2) v16 = hs @ Wv^T  (fp16 only)
    gemm_h16_kernel<<<dim3(Pp / BNh, Mm / BMh), 256, GH_SMEM>>>(
        hs16, wv16, nullptr, nullptr, nullptr, v16, Pp, Hh, nullptr, nullptr);

    // 3) y1 = shift(hs) @ w1a^T + hs @ w1b^T + b1  (fp32 + fp16 mirror)
    gemm_h16_kernel<<<dim3(H2 / BNh, Mm / BMh), 256, GH_SMEM>>>(
        hs16, w1a16, hs16, w1b16, y1, y1h, H2, Hh, conv1_b, lf1c16);

    // 4) y2 = shift(y1) @ w2a^T + y1 @ w2b^T + b2
    gemm_h16_kernel<<<dim3(Hh / BNh, Mm / BMh), 256, GH_SMEM>>>(
        y1h, w2a16, y1h, w2b16, lfout, nullptr, Hh, H2, conv2_b, lf2c16);

    // 5) lf16 = rmsnorm(y2 + hs) * ln_w
    rmsnorm_kernel<<<Mm, 256>>>(lfout, hs, ln_w, lf16);

    // 6) qk = lf16 @ Wqk^T  (fp32 out for rope)
    gemm_h16_kernel<<<dim3(QKW / BNh, Mm / BMh), 256, GH_SMEM>>>(
        lf16, wqk16, nullptr, nullptr, qk, nullptr, QKW, Hh, nullptr, nullptr);

    // 7) RoPE -> fp16 hi/lo Q (scaled) and K
    rope2_kernel<<<Mm * NHh, 128>>>(qk, freqs, pos, qhi, qlo, khi, klo);

    // 8) fp16 flash attention -> attn16
    flash2_kernel<<<dim3(Ss / F2Q, NHh, Bb), 256, F2_SMEM>>>(
        qhi, qlo, khi, klo, v16, attn16);

    // 9) output = attn16 @ Wo^T  (fp32 out)
    gemm_h16_kernel<<<dim3(Hh / BNh, Mm / BMh), 256, GH_SMEM>>>(
        attn16, wo16, nullptr, nullptr, out, nullptr, Hh, Pp, nullptr, nullptr);

    // 10) tails
    tails_kernel<<<(Bb * Hh + 255) / 256, 256>>>(hs, y1, out);
}

// round 14
// speedup vs baseline: 2.5043x; 1.3252x over previous
#include <cuda_runtime.h>
#include <cuda_fp16.h>
#include <cuda_bf16.h>
#include <cstdint>
#include <cstddef>

// Problem constants
#define Bb   2
#define Ss   2048
#define Hh   2048
#define NHh  16
#define HDd  128
#define Pp   2048
#define Mm   (Bb * Ss)          // 4096 rows
#define H2   (Hh / 2)           // 1024
#define QKW  (2 * Pp)           // 4096 (qk row width)
#define MW16 (NHh * HDd)        // 2048 (fp16 q/k buffer row width)
#define EPSc 1e-6f

// ---------------- scratch (static device globals; no allocation) ----------------
__device__ float g_y1[(size_t)Mm * H2];
__device__ float g_lfout[(size_t)Mm * Hh];
__device__ float g_qk[(size_t)Mm * QKW];
__device__ __half g_hs16[(size_t)Mm * Hh];
__device__ __half g_wv16[(size_t)Pp * Hh];
__device__ __half g_wqk16[(size_t)QKW * Hh];
__device__ __half g_wo16[(size_t)Hh * Pp];
__device__ __half g_w1a16[(size_t)H2 * Hh];
__device__ __half g_w1b16[(size_t)H2 * Hh];
__device__ __half g_w2a16[(size_t)Hh * H2];
__device__ __half g_w2b16[(size_t)Hh * H2];
__device__ __half g_y1h[(size_t)Mm * H2];
__device__ __half g_lf16[(size_t)Mm * Hh];
__device__ __half g_v16[(size_t)Mm * Pp];
__device__ __half g_attn16[(size_t)Mm * Pp];
__device__ __half g_lf1c16[(size_t)Bb * Hh];
__device__ __half g_lf2c16[(size_t)Bb * H2];
__device__ __half g_qhi[(size_t)Mm * MW16];
__device__ __half g_qlo[(size_t)Mm * MW16];
__device__ __half g_khi[(size_t)Mm * MW16];
__device__ __half g_klo[(size_t)Mm * MW16];

// ---------------- helpers ----------------
__device__ __forceinline__ void mma_f16(float* d, const uint32_t* a, const uint32_t* b) {
    asm volatile(
        "mma.sync.aligned.m16n8k16.row.col.f32.f16.f16.f32 "
        "{%0,%1,%2,%3},{%4,%5,%6,%7},{%8,%9},{%0,%1,%2,%3};"
        : "+f"(d[0]), "+f"(d[1]), "+f"(d[2]), "+f"(d[3])
        : "r"(a[0]), "r"(a[1]), "r"(a[2]), "r"(a[3]), "r"(b[0]), "r"(b[1]));
}

__device__ __forceinline__ void ldsm4(uint32_t* r, uint32_t saddr) {
    asm volatile("ldmatrix.sync.aligned.m8n8.x4.shared.b16 {%0,%1,%2,%3}, [%4];"
        : "=r"(r[0]), "=r"(r[1]), "=r"(r[2]), "=r"(r[3]) : "r"(saddr));
}

__device__ __forceinline__ void ldsm4t(uint32_t* r, uint32_t saddr) {
    asm volatile("ldmatrix.sync.aligned.m8n8.x4.trans.shared.b16 {%0,%1,%2,%3}, [%4];"
        : "=r"(r[0]), "=r"(r[1]), "=r"(r[2]), "=r"(r[3]) : "r"(saddr));
}

__device__ __forceinline__ uint32_t h2pack(float lo, float hi) {
    __half2 h = __floats2half2_rn(lo, hi);
    return *reinterpret_cast<uint32_t*>(&h);
}

__device__ __forceinline__ void cp16(uint32_t* smem, const void* g) {
    uint32_t s = (uint32_t)__cvta_generic_to_shared(smem);
    asm volatile("cp.async.ca.shared.global [%0], [%1], 16;" :: "r"(s), "l"(g));
}

// ---------------- fp32 -> fp16 conversion ----------------
__global__ void cvt16_kernel(const float* __restrict__ in, __half* __restrict__ out, int n)
{
    int i = (blockIdx.x * 256 + threadIdx.x) * 8;
    if (i < n) {
        float4 f0 = *(const float4*)(in + i);
        float4 f1 = *(const float4*)(in + i + 4);
        uint4 u;
        u.x = h2pack(f0.x, f0.y); u.y = h2pack(f0.z, f0.w);
        u.z = h2pack(f1.x, f1.y); u.w = h2pack(f1.z, f1.w);
        *(uint4*)(out + i) = u;
    }
}

// ---------------- deinterleave conv weights -> fp16 ----------------
__global__ void deint16_kernel(const float* __restrict__ in, __half* __restrict__ a,
                               __half* __restrict__ b, int n)
{
    int i = blockIdx.x * 256 + threadIdx.x;
    if (i < n) {
        a[i] = __float2half_rn(in[2 * i]);
        b[i] = __float2half_rn(in[2 * i + 1]);
    }
}

// ========== FP16 tensor-core GEMM (NT), cp.async 4-stage pipeline + ldmatrix ==========
#define BMh 128
#define BNh 128
#define BKh 32
#define PWH 20
#define NSTG 4
#define STG_W (BMh * PWH)
#define GH_SMEM (NSTG * STG_W * 2 * 4)         // 81920 bytes

__global__ __launch_bounds__(256, 2) void gemm_h16_kernel(
    const __half* __restrict__ A, const __half* __restrict__ W,
    const __half* __restrict__ A2, const __half* __restrict__ W2,
    float* __restrict__ C, __half* __restrict__ C16,
    int N, int K, const float* __restrict__ bias,
    const __half* __restrict__ shiftCache)
{
    extern __shared__ uint32_t sh[];
    uint32_t* Abase = sh;
    uint32_t* Bbase = sh + NSTG * STG_W;
    const uint32_t sb4 = (uint32_t)__cvta_generic_to_shared(sh);

    const int tid = threadIdx.x;
    const int lane = tid & 31;
    const int warp = tid >> 5;
    const int wm = warp >> 2;
    const int wn = warp & 3;
    const int bm = blockIdx.y * BMh;
    const int bn = blockIdx.x * BNh;
    const int mBase = wm * 64;
    const int nBase = wn * 32;

    const int ra = tid >> 1;
    const int seg = tid & 1;
    const int sk = seg * 16;
    const int sw = seg * 8;

    const __half* arow;
    {
        int m = bm + ra;
        if (shiftCache) {
            arow = (m % Ss == 0) ? (shiftCache + (size_t)(m / Ss) * K)
                                 : (A + (size_t)(m - 1) * K);
        } else {
            arow = A + (size_t)m * K;
        }
    }
    const __half* wrow  = W + (size_t)(bn + ra) * K;
    const __half* a2row = A2 ? (A2 + (size_t)(bm + ra) * K) : nullptr;
    const __half* w2row = W2 ? (W2 + (size_t)(bn + ra) * K) : nullptr;

    float acc[4][4][4];
#pragma unroll
    for (int mi = 0; mi < 4; mi++)
#pragma unroll
        for (int ni = 0; ni < 4; ni++)
#pragma unroll
            for (int e = 0; e < 4; e++) acc[mi][ni][e] = 0.f;

    const int nk = K / BKh;
    const int nkt = A2 ? (2 * nk) : nk;

    auto issue = [&](int kt) {
        const __half* ap;
        const __half* wp;
        if (kt < nk) { ap = arow  + kt * BKh + sk;        wp = wrow  + kt * BKh + sk; }
        else         { ap = a2row + (kt - nk) * BKh + sk; wp = w2row + (kt - nk) * BKh + sk; }
        uint32_t* as = Abase + (kt % NSTG) * STG_W + ra * PWH + sw;
        uint32_t* bs = Bbase + (kt % NSTG) * STG_W + ra * PWH + sw;
        cp16(as,     ap);
        cp16(as + 4, ap + 8);
        cp16(bs,     wp);
        cp16(bs + 4, wp + 8);
    };

#pragma unroll
    for (int s = 0; s < NSTG - 1; s++) {
        if (s < nkt) issue(s);
        asm volatile("cp.async.commit_group;");
    }

    const int row4 = lane >> 2;
    const int col4 = lane & 3;
    const int lane15 = lane & 15;
    const int lhi4 = (lane >> 4) << 2;   // word offset 0 or 4

    // per-lane ldmatrix byte offsets (relative to stage base)
    const uint32_t aoff_l = ((mBase + lane15) * PWH + lhi4) * 4;
    const uint32_t boff_l = ((nBase + lane15) * PWH + lhi4) * 4;
    const uint32_t Bbase_b = (uint32_t)(NSTG * STG_W * 4);

    for (int kt = 0; kt < nkt; kt++) {
        asm volatile("cp.async.wait_group %0;" :: "n"(NSTG - 2));
        __syncthreads();

        if (kt + NSTG - 1 < nkt) issue(kt + NSTG - 1);
        asm volatile("cp.async.commit_group;");

        const uint32_t stg = (uint32_t)((kt % NSTG) * STG_W * 4);
        const uint32_t aS = sb4 + stg + aoff_l;
        const uint32_t bS = sb4 + Bbase_b + stg + boff_l;
#pragma unroll
        for (int kw = 0; kw < 16; kw += 8) {
            uint32_t af[4][4], bp[2][4];
#pragma unroll
            for (int mi = 0; mi < 4; mi++)
                ldsm4(af[mi], aS + (mi * 16 * PWH + kw) * 4);
#pragma unroll
            for (int nia = 0; nia < 2; nia++)
                ldsm4(bp[nia], bS + (nia * 16 * PWH + kw) * 4);
            // bp[nia]: r0=b[2nia][0], r1=b[2nia+1][0], r2=b[2nia][1], r3=b[2nia+1][1]
#pragma unroll
            for (int nia = 0; nia < 2; nia++) {
                uint32_t b0[2] = {bp[nia][0], bp[nia][2]};
                uint32_t b1[2] = {bp[nia][1], bp[nia][3]};
#pragma unroll
                for (int mi = 0; mi < 4; mi++) {
                    mma_f16(acc[mi][2 * nia],     af[mi], b0);
                    mma_f16(acc[mi][2 * nia + 1], af[mi], b1);
                }
            }
        }
    }

#pragma unroll
    for (int mi = 0; mi < 4; mi++) {
        int r = bm + mBase + mi * 16 + row4;
#pragma unroll
        for (int ni = 0; ni < 4; ni++) {
            int cb = bn + nBase + ni * 8 + 2 * col4;
            float2 b2 = make_float2(0.f, 0.f);
            if (bias) { b2.x = bias[cb]; b2.y = bias[cb + 1]; }
            float2 v0 = make_float2(acc[mi][ni][0] + b2.x, acc[mi][ni][1] + b2.y);
            float2 v1 = make_float2(acc[mi][ni][2] + b2.x, acc[mi][ni][3] + b2.y);
            if (C) {
                *(float2*)(C + (size_t)r * N + cb) = v0;
                *(float2*)(C + (size_t)(r + 8) * N + cb) = v1;
            }
            if (C16) {
                *(uint32_t*)(C16 + (size_t)r * N + cb) = h2pack(v0.x, v0.y);
                *(uint32_t*)(C16 + (size_t)(r + 8) * N + cb) = h2pack(v1.x, v1.y);
            }
        }
    }
}

// ---------------- residual add + RMSNorm -> fp16 output ----------------
__global__ __launch_bounds__(256) void rmsnorm_kernel(
    const float* __restrict__ y2, const float* __restrict__ x,
    const float* __restrict__ w, __half* __restrict__ out16)
{
    int m = blockIdx.x;
    const float* yrow = y2 + (size_t)m * Hh;
    const float* xrow = x + (size_t)m * Hh;

    float ss = 0.f;
    for (int i = threadIdx.x; i < Hh; i += 256) {
        float t = yrow[i] + xrow[i];
        ss += t * t;
    }
#pragma unroll
    for (int off = 16; off > 0; off >>= 1)
        ss += __shfl_xor_sync(0xffffffffu, ss, off);

    __shared__ float red[9];
    int lane = threadIdx.x & 31, wid = threadIdx.x >> 5;
    if (lane == 0) red[wid] = ss;
    __syncthreads();
    if (threadIdx.x == 0) {
        float tot = 0.f;
        for (int i = 0; i < 8; i++) tot += red[i];
        red[8] = rsqrtf(tot / (float)Hh + EPSc);
    }
    __syncthreads();
    float inv = red[8];
    __half* orow = out16 + (size_t)m * Hh;
    for (int i = threadIdx.x; i < Hh; i += 256) {
        float t = (yrow[i] + xrow[i]) * w[i] * inv;
        orow[i] = __float2half_rn(t);
    }
}

// ---------------- RoPE: qk fp32 -> fp16 hi/lo buffers (Q scaled) ----------------
__global__ __launch_bounds__(128) void rope2_kernel(
    const float* __restrict__ qkbuf, const float* __restrict__ freqs,
    const int* __restrict__ positions,
    __half* __restrict__ qhi, __half* __restrict__ qlo,
    __half* __restrict__ khi, __half* __restrict__ klo)
{
    int mh = blockIdx.x;
    int m = mh / NHh, h = mh % NHh;
    int pos = positions[m];
    int t = threadIdx.x;
    int isK = t >> 6;
    int d = t & 63;

    size_t base = (size_t)m * QKW + (size_t)h * 256 + (size_t)isK * 128;
    float f1 = freqs[(size_t)pos * HDd + d];
    float f2 = freqs[(size_t)pos * HDd + d + 64];
    float c1 = cosf(f1), s1 = sinf(f1);
    float c2 = cosf(f2), s2 = sinf(f2);
    float x1 = qkbuf[base + d];
    float x2 = qkbuf[base + d + 64];
    float r1 = x1 * c1 - x2 * s1;
    float r2 = x2 * c2 + x1 * s2;

    const float scale = 0.08838834764831845f;
    size_t o = (size_t)m * MW16 + (size_t)h * HDd + d;
    if (isK == 0) {
        float a1 = r1 * scale, a2 = r2 * scale;
        __half h1 = __float2half_rn(a1);
        __half h2 = __float2half_rn(a2);
        qhi[o]      = h1;  qlo[o]      = __float2half_rn(a1 - __half2float(h1));
        qhi[o + 64] = h2;  qlo[o + 64] = __float2half_rn(a2 - __half2float(h2));
    } else {
        __half h1 = __float2half_rn(r1);
        __half h2 = __float2half_rn(r2);
        khi[o]      = h1;  klo[o]      = __float2half_rn(r1 - __half2float(h1));
        khi[o + 64] = h2;  klo[o + 64] = __float2half_rn(r2 - __half2float(h2));
    }
}

// ---------------- fp16 tensor-core causal flash attention (ldmatrix edition) ----------------
// TQ=128 (8 warps x 16 rows), TK=32. QK = 3x fp16 hi/lo, PV = fp16.
// cp.async staging; V staged raw [kv][d] and read via ldmatrix.trans.
#define F2Q 128
#define F2K 32
#define PQ 68    // words per Q/K/V smem row (64 data + 4 pad)
#define PV 20    // words per Ps smem row (16 data + 4 pad)
#define Q_SZ (F2Q * PQ)          // 8704 words
#define K_SZ (F2K * PQ)          // 2176 words
#define P_SZ (F2Q * PV)          // 2560 words
#define F2_SMEM ((2 * Q_SZ + 3 * K_SZ + P_SZ) * 4)   // 105984 bytes

__global__ __launch_bounds__(256, 2) void flash2_kernel(
    const __half* __restrict__ qhi_g, const __half* __restrict__ qlo_g,
    const __half* __restrict__ khi_g, const __half* __restrict__ klo_g,
    const __half* __restrict__ v16, __half* __restrict__ attn16)
{
    extern __shared__ uint32_t fsm[];
    uint32_t* Qhi = fsm;                 // word offsets
    uint32_t* Qlo = Qhi + Q_SZ;
    uint32_t* Khi = Qlo + Q_SZ;
    uint32_t* Klo = Khi + K_SZ;
    uint32_t* Vr  = Klo + K_SZ;          // raw V [kv][d]
    uint32_t* Ps  = Vr  + K_SZ;
    const uint32_t sb4 = (uint32_t)__cvta_generic_to_shared(fsm);

    const int qt = gridDim.x - 1 - blockIdx.x;
    const int h  = blockIdx.y;
    const int b  = blockIdx.z;
    const int q0 = qt * F2Q;
    const int tid  = threadIdx.x;
    const int lane = tid & 31;
    const int warp = tid >> 5;
    const int wm16 = warp * 16;
    const int row4 = lane >> 2;
    const int col4 = lane & 3;
    const int lane15 = lane & 15;
    const int lhi4 = (lane >> 4) << 2;     // word offset 0/4
    const int bS = b * Ss;
    const int hq = h * HDd;

    // ---- stage Q (hi+lo), cp.async ----
    for (int c = tid; c < F2Q * 16; c += 256) {
        int row = c >> 4, ch = c & 15;
        size_t g = (size_t)(bS + q0 + row) * MW16 + hq + ch * 8;
        cp16(Qhi + row * PQ + ch * 4, qhi_g + g);
        cp16(Qlo + row * PQ + ch * 4, qlo_g + g);
    }
    asm volatile("cp.async.commit_group;");

    // per-lane ldmatrix byte addresses
    const uint32_t qa_hi = sb4 + (((wm16 + lane15) * PQ + lhi4)) * 4;
    const uint32_t qa_lo = qa_hi + Q_SZ * 4;
    const uint32_t ka_hi = sb4 + (2 * Q_SZ + lane15 * PQ + lhi4) * 4;
    const uint32_t ka_lo = ka_hi + K_SZ * 4;
    // V trans: rows kv = kvs16 + lane15, d byte = nia*32 + ((lane>>4)<<4)
    const uint32_t va    = sb4 + (2 * Q_SZ + 2 * K_SZ) * 4
                         + (uint32_t)(lane15 * PQ) * 4 + ((lane >> 4) << 4);
    const uint32_t pa_a  = sb4 + (2 * Q_SZ + 3 * K_SZ) * 4
                         + (((wm16 + lane15) * PV + lhi4)) * 4;

    float O[16][4];
#pragma unroll
    for (int ni = 0; ni < 16; ni++)
#pragma unroll
        for (int e = 0; e < 4; e++) O[ni][e] = 0.f;
    float mrow0 = -1e30f, mrow1 = -1e30f, lrow0 = 0.f, lrow1 = 0.f;

    const int kend = q0 + F2Q;
    for (int j0 = 0; j0 < kend; j0 += F2K) {
        __syncthreads();
        // K hi/lo + raw V via cp.async
        for (int c = tid; c < F2K * 16; c += 256) {
            int row = c >> 4, ch = c & 15;
            size_t g = (size_t)(bS + j0 + row) * MW16 + hq + ch * 8;
            cp16(Khi + row * PQ + ch * 4, khi_g + g);
            cp16(Klo + row * PQ + ch * 4, klo_g + g);
            cp16(Vr  + row * PQ + ch * 4,
                 v16 + (size_t)(bS + j0 + row) * Pp + hq + ch * 8);
        }
        asm volatile("cp.async.commit_group;");
        asm volatile("cp.async.wait_group 0;");
        __syncthreads();

        bool active = (j0 <= q0 + wm16 + 15);   // warp-uniform
        if (active) {
            // ---- S = Q K^T (3x fp16 hi/lo) ----
            float s[4][4];
#pragma unroll
            for (int ni = 0; ni < 4; ni++)
#pragma unroll
                for (int e = 0; e < 4; e++) s[ni][e] = 0.f;

#pragma unroll
            for (int kw = 0; kw < 64; kw += 8) {
                uint32_t ahi[4], alo[4];
                ldsm4(ahi, qa_hi + kw * 4);
                ldsm4(alo, qa_lo + kw * 4);
#pragma unroll
                for (int nia = 0; nia < 2; nia++) {
                    uint32_t bh[4], bl[4];
                    ldsm4(bh, ka_hi + (nia * 16 * PQ + kw) * 4);
                    ldsm4(bl, ka_lo + (nia * 16 * PQ + kw) * 4);
                    uint32_t bh0[2] = {bh[0], bh[2]}, bh1[2] = {bh[1], bh[3]};
                    uint32_t bl0[2] = {bl[0], bl[2]}, bl1[2] = {bl[1], bl[3]};
                    mma_f16(s[2 * nia],     ahi, bh0);
                    mma_f16(s[2 * nia],     alo, bh0);
                    mma_f16(s[2 * nia],     ahi, bl0);
                    mma_f16(s[2 * nia + 1], ahi, bh1);
                    mma_f16(s[2 * nia + 1], alo, bh1);
                    mma_f16(s[2 * nia + 1], ahi, bl1);
                }
            }

            // ---- causal mask ----
            if (j0 + F2K - 1 > q0 + wm16) {
                int qlo_i = q0 + wm16 + row4;
                int qhi_i = qlo_i + 8;
#pragma unroll
                for (int ni = 0; ni < 4; ni++) {
                    int kp = j0 + ni * 8 + 2 * col4;
                    if (kp     > qlo_i) s[ni][0] = -1e30f;
                    if (kp + 1 > qlo_i) s[ni][1] = -1e30f;
                    if (kp     > qhi_i) s[ni][2] = -1e30f;
                    if (kp + 1 > qhi_i) s[ni][3] = -1e30f;
                }
            }

            // ---- online softmax ----
            float mx0 = -1e30f, mx1 = -1e30f;
#pragma unroll
            for (int ni = 0; ni < 4; ni++) {
                mx0 = fmaxf(mx0, fmaxf(s[ni][0], s[ni][1]));
                mx1 = fmaxf(mx1, fmaxf(s[ni][2], s[ni][3]));
            }
            mx0 = fmaxf(mx0, __shfl_xor_sync(0xffffffffu, mx0, 1));
            mx0 = fmaxf(mx0, __shfl_xor_sync(0xffffffffu, mx0, 2));
            mx1 = fmaxf(mx1, __shfl_xor_sync(0xffffffffu, mx1, 1));
            mx1 = fmaxf(mx1, __shfl_xor_sync(0xffffffffu, mx1, 2));
            float mn0 = fmaxf(mrow0, mx0), mn1 = fmaxf(mrow1, mx1);
            float al0 = __expf(mrow0 - mn0), al1 = __expf(mrow1 - mn1);
            mrow0 = mn0; mrow1 = mn1;

            float sum0 = 0.f, sum1 = 0.f;
            int pb0 = (wm16 + row4) * PV;
            int pb1 = (wm16 + row4 + 8) * PV;
#pragma unroll
            for (int ni = 0; ni < 4; ni++) {
                float p0 = __expf(s[ni][0] - mn0);
                float p1 = __expf(s[ni][1] - mn0);
                float p2 = __expf(s[ni][2] - mn1);
                float p3 = __expf(s[ni][3] - mn1);
                sum0 += p0 + p1; sum1 += p2 + p3;
                Ps[pb0 + ni * 4 + col4] = h2pack(p0, p1);
                Ps[pb1 + ni * 4 + col4] = h2pack(p2, p3);
            }
            lrow0 = lrow0 * al0 + sum0;
            lrow1 = lrow1 * al1 + sum1;
#pragma unroll
            for (int ni = 0; ni < 16; ni++) {
                O[ni][0] *= al0; O[ni][1] *= al0;
                O[ni][2] *= al1; O[ni][3] *= al1;
            }
            __syncwarp();   // Ps rows warp-private

            // ---- O += P V  (V read transposed via ldmatrix.trans) ----
#pragma unroll
            for (int kvs = 0; kvs < 2; kvs++) {           // kv chunks of 16
                uint32_t a[4];
                ldsm4(a, pa_a + kvs * 8 * 4);
                uint32_t vrow = va + (uint32_t)(kvs * 16 * PQ) * 4;
#pragma unroll
                for (int nia = 0; nia < 8; nia++) {
                    uint32_t bv[4];
                    ldsm4t(bv, vrow + nia * 32);
                    // bv: r0=b[2nia][0], r1=b[2nia][1], r2=b[2nia+1][0], r3=b[2nia+1][1]
                    mma_f16(O[2 * nia],     a, &bv[0]);
                    mma_f16(O[2 * nia + 1], a, &bv[2]);
                }
            }
        }
    }

    // ---- finalize ----
    lrow0 += __shfl_xor_sync(0xffffffffu, lrow0, 1);
    lrow0 += __shfl_xor_sync(0xffffffffu, lrow0, 2);
    lrow1 += __shfl_xor_sync(0xffffffffu, lrow1, 1);
    lrow1 += __shfl_xor_sync(0xffffffffu, lrow1, 2);
    float inv0 = 1.f / lrow0, inv1 = 1.f / lrow1;

    size_t ob0 = (size_t)(bS + q0 + wm16 + row4) * Pp + hq;
    size_t ob1 = ob0 + (size_t)8 * Pp;
#pragma unroll
    for (int ni = 0; ni < 16; ni++) {
        int cb = ni * 8 + 2 * col4;
        *(uint32_t*)(attn16 + ob0 + cb) = h2pack(O[ni][0] * inv0, O[ni][1] * inv0);
        *(uint32_t*)(attn16 + ob1 + cb) = h2pack(O[ni][2] * inv1, O[ni][3] * inv1);
    }
}

// ---------------- tail outputs ----------------
__global__ void tails_kernel(const float* __restrict__ hs, const float* __restrict__ y1,
                             float* __restrict__ out)
{
    int i = blockIdx.x * 256 + threadIdx.x;
    size_t off1 = (size_t)Mm * Hh;
    size_t off2 = off1 + (size_t)Bb * Hh;
    if (i < Bb * Hh) {
        int b = i / Hh, hh = i % Hh;
        out[off1 + i] = hs[((size_t)b * Ss + (Ss - 1)) * Hh + hh];
    }
    if (i < Bb * H2) {
        int b = i / H2, oo = i % H2;
        out[off2 + i] = y1[((size_t)b * Ss + (Ss - 1)) * H2 + oo];
    }
}

// ---------------- launch ----------------
extern "C" void kernel_launch(void* const* d_in, const int* in_sizes, int n_in,
                              void* d_out, int out_size)
{
    (void)in_sizes; (void)n_in; (void)out_size;
    const float* hs      = (const float*)d_in[0];
    const float* freqs   = (const float*)d_in[1];
    const int*   pos     = (const int*)  d_in[2];
    const float* Wqk     = (const float*)d_in[3];
    const float* Wv      = (const float*)d_in[4];
    const float* Wo      = (const float*)d_in[5];
    const float* conv1_w = (const float*)d_in[6];
    const float* conv1_b = (const float*)d_in[7];
    const float* conv2_w = (const float*)d_in[8];
    const float* conv2_b = (const float*)d_in[9];
    const float* ln_w    = (const float*)d_in[10];
    const float* lf1c    = (const float*)d_in[11];
    const float* lf2c    = (const float*)d_in[12];
    float* out = (float*)d_out;

    float *y1, *lfout, *qk;
    __half *hs16, *wv16, *wqk16, *wo16, *w1a16, *w1b16, *w2a16, *w2b16;
    __half *y1h, *lf16, *v16, *attn16, *lf1c16, *lf2c16;
    __half *qhi, *qlo, *khi, *klo;
    cudaGetSymbolAddress((void**)&y1,     g_y1);
    cudaGetSymbolAddress((void**)&lfout,  g_lfout);
    cudaGetSymbolAddress((void**)&qk,     g_qk);
    cudaGetSymbolAddress((void**)&hs16,   g_hs16);
    cudaGetSymbolAddress((void**)&wv16,   g_wv16);
    cudaGetSymbolAddress((void**)&wqk16,  g_wqk16);
    cudaGetSymbolAddress((void**)&wo16,   g_wo16);
    cudaGetSymbolAddress((void**)&w1a16,  g_w1a16);
    cudaGetSymbolAddress((void**)&w1b16,  g_w1b16);
    cudaGetSymbolAddress((void**)&w2a16,  g_w2a16);
    cudaGetSymbolAddress((void**)&w2b16,  g_w2b16);
    cudaGetSymbolAddress((void**)&y1h,    g_y1h);
    cudaGetSymbolAddress((void**)&lf16,   g_lf16);
    cudaGetSymbolAddress((void**)&v16,    g_v16);
    cudaGetSymbolAddress((void**)&attn16, g_attn16);
    cudaGetSymbolAddress((void**)&lf1c16, g_lf1c16);
    cudaGetSymbolAddress((void**)&lf2c16, g_lf2c16);
    cudaGetSymbolAddress((void**)&qhi,    g_qhi);
    cudaGetSymbolAddress((void**)&qlo,    g_qlo);
    cudaGetSymbolAddress((void**)&khi,    g_khi);
    cudaGetSymbolAddress((void**)&klo,    g_klo);

    static bool attr_done = false;
    if (!attr_done) {
        cudaFuncSetAttribute(flash2_kernel,
                             cudaFuncAttributeMaxDynamicSharedMemorySize, F2_SMEM);
        cudaFuncSetAttribute(gemm_h16_kernel,
                             cudaFuncAttributeMaxDynamicSharedMemorySize, GH_SMEM);
        attr_done = true;
    }

    // 1) fp16 operand prep
    cvt16_kernel<<<(Mm * Hh / 8 + 255) / 256, 256>>>(hs, hs16, Mm * Hh);
    cvt16_kernel<<<(Pp * Hh / 8 + 255) / 256, 256>>>(Wv, wv16, Pp * Hh);
    cvt16_kernel<<<(QKW * Hh / 8 + 255) / 256, 256>>>(Wqk, wqk16, QKW * Hh);
    cvt16_kernel<<<(Hh * Pp / 8 + 255) / 256, 256>>>(Wo, wo16, Hh * Pp);
    cvt16_kernel<<<(Bb * Hh / 8 + 255) / 256, 256>>>(lf1c, lf1c16, Bb * Hh);
    cvt16_kernel<<<(Bb * H2 / 8 + 255) / 256, 256>>>(lf2c, lf2c16, Bb * H2);
    deint16_kernel<<<(H2 * Hh + 255) / 256, 256>>>(conv1_w, w1a16, w1b16, H2 * Hh);
    deint16_kernel<<<(Hh * H2 + 255) / 256, 256>>>(conv2_w, w2a16, w2b16, Hh * H2);

    // 2) v16 = hs @ Wv^T  (fp16 only)
    gemm_h16_kernel<<<dim3(Pp / BNh, Mm / BMh), 256, GH_SMEM>>>(
        hs16, wv16, nullptr, nullptr, nullptr, v16, Pp, Hh, nullptr, nullptr);

    // 3) y1 = shift(hs) @ w1a^T + hs @ w1b^T + b1  (fp32 + fp16 mirror)
    gemm_h16_kernel<<<dim3(H2 / BNh, Mm / BMh), 256, GH_SMEM>>>(
        hs16, w1a16, hs16, w1b16, y1, y1h, H2, Hh, conv1_b, lf1c16);

    // 4) y2 = shift(y1) @ w2a^T + y1 @ w2b^T + b2
    gemm_h16_kernel<<<dim3(Hh / BNh, Mm / BMh), 256, GH_SMEM>>>(
        y1h, w2a16, y1h, w2b16, lfout, nullptr, Hh, H2, conv2_b, lf2c16);

    // 5) lf16 = rmsnorm(y2 + hs) * ln_w
    rmsnorm_kernel<<<Mm, 256>>>(lfout, hs, ln_w, lf16);

    // 6) qk = lf16 @ Wqk^T  (fp32 out for rope)
    gemm_h16_kernel<<<dim3(QKW / BNh, Mm / BMh), 256, GH_SMEM>>>(
        lf16, wqk16, nullptr, nullptr, qk, nullptr, QKW, Hh, nullptr, nullptr);

    // 7) RoPE -> fp16 hi/lo Q (scaled) and K
    rope2_kernel<<<Mm * NHh, 128>>>(qk, freqs, pos, qhi, qlo, khi, klo);

    // 8) fp16 flash attention -> attn16
    flash2_kernel<<<dim3(Ss / F2Q, NHh, Bb), 256, F2_SMEM>>>(
        qhi, qlo, khi, klo, v16, attn16);

    // 9) output = attn16 @ Wo^T  (fp32 out)
    gemm_h16_kernel<<<dim3(Hh / BNh, Mm / BMh), 256, GH_SMEM>>>(
        attn16, wo16, nullptr, nullptr, out, nullptr, Hh, Pp, nullptr, nullptr);

    // 10) tails
    tails_kernel<<<(Bb * Hh + 255) / 256, 256>>>(hs, y1, out);
}